// round 12
// baseline (speedup 1.0000x reference)
#include <cuda_runtime.h>
#include <cuda_bf16.h>
#include <cuda_fp16.h>
#include <math.h>
#include <stdint.h>

// Problem constants
#define BATCH 2
#define SEQ   2048
#define CDIM  2048
#define NHEAD 16
#define NKV   4
#define HDIM  128
#define HALF  64
#define MROWS (BATCH*SEQ)          // 4096
#define QW    (NHEAD*HDIM)         // 2048
#define KW    (NKV*HDIM)           // 512

// ---------------------------------------------------------------------------
// Scratch (device globals; no allocations allowed)
// ---------------------------------------------------------------------------
__device__ __half g_x2  [4096 * 4096];            // 32 MB fp16 [hi|lo] (x; later attn-out)
__device__ __half g_wqkv[3072 * 2048];            // 12 MB packed [Wq|Wk|Wv]^T fp16
__device__ __half g_wo2 [2048 * 2048];            // 8 MB Wo^T fp16
__device__ __half g_qh[MROWS * QW];               // 16 MB fp16 q hi
__device__ __half g_ql[MROWS * QW];               // 16 MB fp16 q lo
__device__ __half g_kh[MROWS * KW];               // 4 MB fp16 k (single)
__device__ __half g_vh[MROWS * KW];               // 4 MB fp16 v (single)

// ---------------------------------------------------------------------------
// Baseline-PTX tensor-core helpers
// ---------------------------------------------------------------------------
__device__ __forceinline__ uint32_t smem_u32_of(const void* p) {
    uint32_t a;
    asm("{ .reg .u64 t; cvta.to.shared.u64 t, %1; cvt.u32.u64 %0, t; }" : "=r"(a) : "l"(p));
    return a;
}
__device__ __forceinline__ void cp_async16(uint32_t saddr, const void* gaddr) {
    asm volatile("cp.async.cg.shared.global [%0], [%1], 16;" :: "r"(saddr), "l"(gaddr));
}
__device__ __forceinline__ void cp_commit() {
    asm volatile("cp.async.commit_group;" ::: "memory");
}
__device__ __forceinline__ void cp_wait1() {
    asm volatile("cp.async.wait_group 1;" ::: "memory");
}
__device__ __forceinline__ void cp_wait0() {
    asm volatile("cp.async.wait_group 0;" ::: "memory");
}
__device__ __forceinline__ void ldmatrix_x4(uint32_t* r, uint32_t addr) {
    asm volatile("ldmatrix.sync.aligned.m8n8.x4.shared.b16 {%0,%1,%2,%3}, [%4];"
                 : "=r"(r[0]), "=r"(r[1]), "=r"(r[2]), "=r"(r[3]) : "r"(addr));
}
__device__ __forceinline__ void ldmatrix_x4_trans(uint32_t* r, uint32_t addr) {
    asm volatile("ldmatrix.sync.aligned.m8n8.x4.trans.shared.b16 {%0,%1,%2,%3}, [%4];"
                 : "=r"(r[0]), "=r"(r[1]), "=r"(r[2]), "=r"(r[3]) : "r"(addr));
}
__device__ __forceinline__ void mma_fp16(float* c, const uint32_t* a, uint32_t b0, uint32_t b1) {
    asm volatile(
        "mma.sync.aligned.m16n8k16.row.col.f32.f16.f16.f32 "
        "{%0,%1,%2,%3}, {%4,%5,%6,%7}, {%8,%9}, {%0,%1,%2,%3};"
        : "+f"(c[0]), "+f"(c[1]), "+f"(c[2]), "+f"(c[3])
        : "r"(a[0]), "r"(a[1]), "r"(a[2]), "r"(a[3]), "r"(b0), "r"(b1));
}

// swizzled smem offsets (16B chunks, XOR row&7)
#define SW256(r, c) ((uint32_t)((r) * 256 + (((c) ^ ((r) & 7)) << 4)))
#define SW128(r, c) ((uint32_t)((r) * 128 + (((c) ^ ((r) & 7)) << 4)))

// fp16 hi/lo split store of 2 consecutive values
__device__ __forceinline__ void split_store2h(__half* oh, __half* ol,
                                              size_t idx, float a, float b) {
    __half h0 = __float2half(a), h1 = __float2half(b);
    __half2 hp = {h0, h1};
    __half2 lp = {__float2half(a - __half2float(h0)),
                  __float2half(b - __half2float(h1))};
    *reinterpret_cast<__half2*>(oh + idx) = hp;
    *reinterpret_cast<__half2*>(ol + idx) = lp;
}
__device__ __forceinline__ void store2h(__half* o, size_t idx, float a, float b) {
    __half2 hp = {__float2half(a), __float2half(b)};
    *reinterpret_cast<__half2*>(o + idx) = hp;
}

// ===========================================================================
// fp16 GEMM core: 128x128 CTA tile, BK=64, 3-stage cp.async pipeline.
// 4 warps (2x2), warp tile 64x64 -> 128 B smem per MMA (was 192).
// A2[M,4096] fp16 [hi|lo] K-major, B[N,2048] fp16 K-major.
// C = Ah*B + Al*B  (2 K-segments, NIT=64).
// ===========================================================================
#define HG_SMEM (3 * 32768)
#define HG_NIT  64
#define HG_THREADS 128

struct GemmFrag { float acc[4][8][4]; };

__device__ __forceinline__ void gemm_mainloop(
    const __half* __restrict__ A2, const __half* __restrict__ B,
    uint32_t su, int m0, int n0, GemmFrag& F)
{
    const int tid  = threadIdx.x;
    const int wid  = tid >> 5;
    const int lane = tid & 31;

    uint32_t smoff[8];
    const __half *gA[8], *gB[8];
#pragma unroll
    for (int i = 0; i < 8; i++) {
        int id = tid + i * 128;
        int r = id >> 3, c = id & 7;
        smoff[i] = (uint32_t)(r * 128 + ((c ^ (r & 7)) << 4));
        gA[i] = A2 + (size_t)(m0 + r) * 4096 + c * 8;
        gB[i] = B  + (size_t)(n0 + r) * 2048 + c * 8;
    }

    const int mwarp = (wid >> 1) * 64;
    const int nwarp = (wid & 1) * 64;

    const int asel = lane >> 3;
    const int arow = (lane & 7) + ((asel & 1) << 3);
    const int akc  = asel >> 1;
    const int brow = (lane & 7) + ((asel >> 1) << 3);
    const int bkc  = asel & 1;

#pragma unroll
    for (int mf = 0; mf < 4; mf++)
#pragma unroll
        for (int nf = 0; nf < 8; nf++)
#pragma unroll
            for (int e = 0; e < 4; e++) F.acc[mf][nf][e] = 0.f;

    auto issue = [&](int it, int stage) {
        int seg = it >> 5;
        int t   = it & 31;
        int aoff = t * 64 + (seg == 1 ? 2048 : 0);
        int boff = t * 64;
        uint32_t ab = su + (uint32_t)stage * 32768u;
        uint32_t bb = ab + 16384u;
#pragma unroll
        for (int i = 0; i < 8; i++) {
            cp_async16(ab + smoff[i], gA[i] + aoff);
            cp_async16(bb + smoff[i], gB[i] + boff);
        }
        cp_commit();
    };

    issue(0, 0);
    issue(1, 1);

    int sCur = 0, sNxt = 2;
    for (int it = 0; it < HG_NIT; ++it) {
        if (it + 1 < HG_NIT) cp_wait1();
        else                 cp_wait0();
        __syncthreads();
        if (it + 2 < HG_NIT) issue(it + 2, sNxt);

        uint32_t abase = su + (uint32_t)sCur * 32768u;
        uint32_t bbase = abase + 16384u;

#pragma unroll
        for (int ks = 0; ks < 4; ++ks) {
            uint32_t br[4][4];
#pragma unroll
            for (int bh = 0; bh < 4; bh++) {
                int R = nwarp + bh * 16 + brow;
                int ch = ks * 2 + bkc;
                ldmatrix_x4(br[bh], bbase + R * 128 + (uint32_t)((ch ^ (R & 7)) << 4));
            }
#pragma unroll
            for (int mf = 0; mf < 4; mf++) {
                uint32_t af[4];
                int R = mwarp + mf * 16 + arow;
                int ch = ks * 2 + akc;
                ldmatrix_x4(af, abase + R * 128 + (uint32_t)((ch ^ (R & 7)) << 4));
#pragma unroll
                for (int bh = 0; bh < 4; bh++) {
                    mma_fp16(F.acc[mf][2 * bh],     af, br[bh][0], br[bh][1]);
                    mma_fp16(F.acc[mf][2 * bh + 1], af, br[bh][2], br[bh][3]);
                }
            }
        }
        sCur = (sCur == 2) ? 0 : sCur + 1;
        sNxt = (sNxt == 2) ? 0 : sNxt + 1;
    }
}

// ---------------------------------------------------------------------------
// Generic GEMM with fp32 output + optional bias (used for Wo).
// ---------------------------------------------------------------------------
__global__ __launch_bounds__(HG_THREADS, 2)
void hgemm_kernel(const __half* __restrict__ A2, const __half* __restrict__ B,
                  float* __restrict__ C, int N, const float* __restrict__ bias)
{
    extern __shared__ __align__(1024) char smem[];
    const uint32_t su = smem_u32_of(smem);
    const int tid  = threadIdx.x;
    const int wid  = tid >> 5;
    const int lane = tid & 31;
    const int m0 = blockIdx.y * 128;
    const int n0 = blockIdx.x * 128;

    GemmFrag F;
    gemm_mainloop(A2, B, su, m0, n0, F);

    const int mwarp = (wid >> 1) * 64;
    const int nwarp = (wid & 1) * 64;
    const int mrow = lane >> 2;
    const int ncol = (lane & 3) * 2;
#pragma unroll
    for (int mf = 0; mf < 4; mf++) {
#pragma unroll
        for (int nf = 0; nf < 8; nf++) {
            int gm = m0 + mwarp + mf * 16 + mrow;
            int gn = n0 + nwarp + nf * 8 + ncol;
            float b0 = 0.f, b1 = 0.f;
            if (bias != nullptr) { b0 = bias[gn]; b1 = bias[gn + 1]; }
            float2 lo = make_float2(F.acc[mf][nf][0] + b0, F.acc[mf][nf][1] + b1);
            float2 hi = make_float2(F.acc[mf][nf][2] + b0, F.acc[mf][nf][3] + b1);
            *reinterpret_cast<float2*>(C + (size_t)gm * N + gn)       = lo;
            *reinterpret_cast<float2*>(C + (size_t)(gm + 8) * N + gn) = hi;
        }
    }
}

// ---------------------------------------------------------------------------
// Fused QKV GEMM + per-head RMSNorm + RoPE + fp16 epilogue.
//   cols [0,2048)    -> q heads: rmsnorm+rope -> qh/ql (fp16 hi/lo)
//   cols [2048,2560) -> k heads: rmsnorm+rope -> kh (fp16 single)
//   cols [2560,3072) -> v: fp16 single -> vh
// ---------------------------------------------------------------------------
__global__ __launch_bounds__(HG_THREADS, 2)
void qkv_gemm_kernel(const __half* __restrict__ A2, const __half* __restrict__ B,
                     const float* __restrict__ cosp, const float* __restrict__ sinp,
                     __half* __restrict__ qh, __half* __restrict__ ql,
                     __half* __restrict__ kh, __half* __restrict__ vh)
{
    extern __shared__ __align__(1024) char smem[];
    const uint32_t su = smem_u32_of(smem);
    const int tid  = threadIdx.x;
    const int wid  = tid >> 5;
    const int lane = tid & 31;
    const int m0 = blockIdx.y * 128;
    const int n0 = blockIdx.x * 128;

    GemmFrag F;
    gemm_mainloop(A2, B, su, m0, n0, F);

    const int mwarp = (wid >> 1) * 64;
    const int nwarp = (wid & 1) * 64;
    const int mrow = lane >> 2;
    const int ncol = (lane & 3) * 2;

    if (n0 >= 2560) {
        // V region: single fp16
#pragma unroll
        for (int mf = 0; mf < 4; mf++)
#pragma unroll
            for (int nf = 0; nf < 8; nf++) {
                int gm = m0 + mwarp + mf * 16 + mrow;
                int gn = n0 - 2560 + nwarp + nf * 8 + ncol;
                store2h(vh, (size_t)gm * 512 + gn,       F.acc[mf][nf][0], F.acc[mf][nf][1]);
                store2h(vh, (size_t)(gm + 8) * 512 + gn, F.acc[mf][nf][2], F.acc[mf][nf][3]);
            }
        return;
    }

    // ---- Q/K region: RMSNorm + RoPE, all in-CTA ----
    __syncthreads();   // pipeline smem no longer needed; safe to reuse
    const int NP = 132;
    float* ntile = reinterpret_cast<float*>(smem);     // [128][132] fp32
    float* ssqp  = ntile + 128 * NP;                   // [2][128]
    float* rmsv  = ssqp + 256;                         // [128]

    // stage fp32 values + per-warp row ssq partials (each warp owns 64 cols)
#pragma unroll
    for (int mf = 0; mf < 4; mf++) {
        int lr0 = mwarp + mf * 16 + mrow;
        int lr1 = lr0 + 8;
        float p0 = 0.f, p1 = 0.f;
#pragma unroll
        for (int nf = 0; nf < 8; nf++) {
            int cc = nwarp + nf * 8 + ncol;
            float a0 = F.acc[mf][nf][0], a1 = F.acc[mf][nf][1];
            float a2 = F.acc[mf][nf][2], a3 = F.acc[mf][nf][3];
            ntile[lr0 * NP + cc]     = a0;
            ntile[lr0 * NP + cc + 1] = a1;
            ntile[lr1 * NP + cc]     = a2;
            ntile[lr1 * NP + cc + 1] = a3;
            p0 += a0 * a0 + a1 * a1;
            p1 += a2 * a2 + a3 * a3;
        }
        p0 += __shfl_xor_sync(0xffffffffu, p0, 1);
        p0 += __shfl_xor_sync(0xffffffffu, p0, 2);
        p1 += __shfl_xor_sync(0xffffffffu, p1, 1);
        p1 += __shfl_xor_sync(0xffffffffu, p1, 2);
        if ((lane & 3) == 0) {
            ssqp[(wid & 1) * 128 + lr0] = p0;
            ssqp[(wid & 1) * 128 + lr1] = p1;
        }
    }
    __syncthreads();
    if (tid < 128) {
        float s = ssqp[tid] + ssqp[128 + tid];
        rmsv[tid] = rsqrtf(s * (1.0f / 128.0f) + 1.1920929e-7f);
    }
    __syncthreads();

    // RoPE + store: 1 thread per row, 64 dims
    {
        int r = tid;
        int gm = m0 + r;
        int t  = gm & (SEQ - 1);
        float rm = rmsv[r];
        const bool isq = (n0 < 2048);
        size_t stride = isq ? 2048 : 512;
        int colbase = isq ? n0 : (n0 - 2048);
        size_t rowoff = (size_t)gm * stride + colbase;
        const float* crow = cosp + t * HALF;
        const float* srow = sinp + t * HALF;
        const float* nrow = ntile + r * NP;
#pragma unroll 8
        for (int d = 0; d < 64; d += 2) {
            float v0a = nrow[d]      * rm, v1a = nrow[d + 64] * rm;
            float v0b = nrow[d + 1]  * rm, v1b = nrow[d + 65] * rm;
            float ca = crow[d],     sa = srow[d];
            float cb = crow[d + 1], sb = srow[d + 1];
            float y0 = v0a * ca - v1a * sa, y1 = v0b * cb - v1b * sb;
            float y2 = v0a * sa + v1a * ca, y3 = v0b * sb + v1b * cb;
            if (isq) {
                split_store2h(qh, ql, rowoff + d,      y0, y1);
                split_store2h(qh, ql, rowoff + 64 + d, y2, y3);
            } else {
                store2h(kh, rowoff + d,      y0, y1);
                store2h(kh, rowoff + 64 + d, y2, y3);
            }
        }
    }
}

// ---------------------------------------------------------------------------
// fp32 -> (hi, lo) fp16 split. src [M, 2048] -> dst [M, 4096] ([hi|lo]).
// ---------------------------------------------------------------------------
__global__ void split2048_kernel(const float* __restrict__ src, __half* __restrict__ dst)
{
    int i = blockIdx.x * 256 + threadIdx.x;
    float4 v = reinterpret_cast<const float4*>(src)[i];
    int e = i * 4;
    int m = e >> 11;
    int k = e & 2047;
    __half* d = dst + (size_t)m * 4096 + k;
    __half h0 = __float2half(v.x), h1 = __float2half(v.y);
    __half h2 = __float2half(v.z), h3 = __float2half(v.w);
    d[0] = h0; d[1] = h1; d[2] = h2; d[3] = h3;
    d[2048] = __float2half(v.x - __half2float(h0));
    d[2049] = __float2half(v.y - __half2float(h1));
    d[2050] = __float2half(v.z - __half2float(h2));
    d[2051] = __float2half(v.w - __half2float(h3));
}

// ---------------------------------------------------------------------------
// Transposed fp16 convert of W [2048, N] into dst columns [nbase, nbase+N),
// K-major [n][2048].
// ---------------------------------------------------------------------------
__device__ __forceinline__ void tconv_body(const float* __restrict__ W,
                                           __half* __restrict__ dst,
                                           int N, int nbase, int bx, int by)
{
    __shared__ float tl[32][33];
    int tx = threadIdx.x, ty = threadIdx.y;
    int n0 = bx * 32, k0 = by * 32;
#pragma unroll
    for (int j = 0; j < 4; j++)
        tl[ty + j * 8][tx] = W[(size_t)(k0 + ty + j * 8) * N + n0 + tx];
    __syncthreads();
#pragma unroll
    for (int j = 0; j < 4; j++) {
        int n = nbase + n0 + ty + j * 8;
        int k = k0 + tx;
        dst[(size_t)n * 2048 + k] = __float2half(tl[tx][ty + j * 8]);
    }
}

__global__ void tconv_qkv_kernel(const float* __restrict__ Wq, const float* __restrict__ Wk,
                                 const float* __restrict__ Wv, __half* __restrict__ dst)
{
    int z = blockIdx.z;
    const float* W = (z == 0) ? Wq : (z == 1) ? Wk : Wv;
    int N     = (z == 0) ? 2048 : 512;
    int nbase = (z == 0) ? 0 : (z == 1) ? 2048 : 2560;
    if ((int)blockIdx.x * 32 >= N) return;
    tconv_body(W, dst, N, nbase, blockIdx.x, blockIdx.y);
}

__global__ void tconv_wo_kernel(const float* __restrict__ W, __half* __restrict__ dst)
{
    tconv_body(W, dst, 2048, 0, blockIdx.x, blockIdx.y);
}

// ---------------------------------------------------------------------------
// fp16 HMMA flash attention, causal, GQA (unchanged from round 11).
//   S = qh*k + ql*k (2 terms).  O += ph*v + pl*v (2 terms).
// ---------------------------------------------------------------------------
#define FA_QHI 0
#define FA_QLO 32768
#define FA_K   65536
#define FA_V   98304
#define FA_PHI 131072
#define FA_PLO 147456
#define FA_SMEM 163840

__global__ __launch_bounds__(256, 1)
void flash_hmma_kernel(const __half* __restrict__ qh, const __half* __restrict__ ql,
                       const __half* __restrict__ kh, const __half* __restrict__ vh,
                       __half* __restrict__ x2)
{
    extern __shared__ __align__(1024) char smem[];
    const uint32_t su = smem_u32_of(smem);
    const int tid  = threadIdx.x;
    const int wid  = tid >> 5;
    const int lane = tid & 31;

    const int qt = (int)gridDim.x - 1 - (int)blockIdx.x;   // long CTAs first
    const int bh = blockIdx.y;
    const int b  = bh >> 4;
    const int h  = bh & 15;
    const int hkv = h >> 2;
    const int q0 = qt * 128;
    const float scale = 0.08838834764831845f;   // 1/sqrt(128)

    const __half* qhb = qh + (size_t)b * SEQ * QW + h * HDIM;
    const __half* qlb = ql + (size_t)b * SEQ * QW + h * HDIM;
    const __half* khb = kh + (size_t)b * SEQ * KW + hkv * HDIM;
    const __half* vhb = vh + (size_t)b * SEQ * KW + hkv * HDIM;

    for (int i = tid; i < 128 * 16; i += 256) {
        int r = i >> 4, c = i & 15;
        *reinterpret_cast<uint4*>(smem + FA_QHI + SW256(r, c)) =
            *reinterpret_cast<const uint4*>(qhb + (size_t)(q0 + r) * QW + c * 8);
        *reinterpret_cast<uint4*>(smem + FA_QLO + SW256(r, c)) =
            *reinterpret_cast<const uint4*>(qlb + (size_t)(q0 + r) * QW + c * 8);
    }

    const int asel = lane >> 3;
    const int arow = (lane & 7) + ((asel & 1) << 3);
    const int akc  = asel >> 1;
    const int brow = (lane & 7) + ((asel >> 1) << 3);
    const int bkc  = asel & 1;
    const int qrow_s = wid * 16 + arow;

    float o[16][4];
#pragma unroll
    for (int g = 0; g < 16; g++)
#pragma unroll
        for (int e = 0; e < 4; e++) o[g][e] = 0.f;
    float m0 = -1e30f, m1 = -1e30f, l0 = 0.f, l1 = 0.f;

    const int ntiles = 2 * qt + 2;

    auto issueKV = [&](int kt) {
        int k0 = kt * 64;
        uint32_t kb = su + FA_K + (uint32_t)(kt & 1) * 16384u;
        uint32_t vb = su + FA_V + (uint32_t)(kt & 1) * 16384u;
#pragma unroll
        for (int i = 0; i < 4; i++) {
            int id = tid + i * 256;
            int r = id >> 4, c = id & 15;
            size_t go = (size_t)(k0 + r) * KW + c * 8;
            uint32_t so = SW256(r, c);
            cp_async16(kb + so, khb + go);
            cp_async16(vb + so, vhb + go);
        }
        cp_commit();
    };

    issueKV(0);

    const int r0g = q0 + wid * 16 + (lane >> 2);
    const int r1g = r0g + 8;
    const int pr0 = wid * 16 + (lane >> 2);
    const int pr1 = pr0 + 8;

    for (int kt = 0; kt < ntiles; ++kt) {
        if (kt + 1 < ntiles) { issueKV(kt + 1); cp_wait1(); }
        else                 { cp_wait0(); }
        __syncthreads();

        uint32_t kb = su + FA_K + (uint32_t)(kt & 1) * 16384u;
        uint32_t vb = su + FA_V + (uint32_t)(kt & 1) * 16384u;

        // ---- S = QK^T (fp16, 2 terms) ----
        float s[8][4];
#pragma unroll
        for (int t = 0; t < 8; t++)
#pragma unroll
            for (int e = 0; e < 4; e++) s[t][e] = 0.f;

#pragma unroll
        for (int d = 0; d < 8; ++d) {
            uint32_t ah[4], al[4];
            ldmatrix_x4(ah, su + FA_QHI + SW256(qrow_s, d * 2 + akc));
            ldmatrix_x4(al, su + FA_QLO + SW256(qrow_s, d * 2 + akc));
#pragma unroll
            for (int j = 0; j < 4; ++j) {
                int R = j * 16 + brow;
                uint32_t kf[4];
                ldmatrix_x4(kf, kb + SW256(R, d * 2 + bkc));
                mma_fp16(s[2 * j],     ah, kf[0], kf[1]);
                mma_fp16(s[2 * j + 1], ah, kf[2], kf[3]);
                mma_fp16(s[2 * j],     al, kf[0], kf[1]);
                mma_fp16(s[2 * j + 1], al, kf[2], kf[3]);
            }
        }

        const int k0 = kt * 64;
        const bool dm = (kt >= 2 * qt);
        float mx0 = -1e30f, mx1 = -1e30f;
#pragma unroll
        for (int t = 0; t < 8; t++) {
            int c0 = k0 + t * 8 + (lane & 3) * 2;
            s[t][0] *= scale; s[t][1] *= scale; s[t][2] *= scale; s[t][3] *= scale;
            if (dm) {
                if (c0     > r0g) s[t][0] = -1e30f;
                if (c0 + 1 > r0g) s[t][1] = -1e30f;
                if (c0     > r1g) s[t][2] = -1e30f;
                if (c0 + 1 > r1g) s[t][3] = -1e30f;
            }
            mx0 = fmaxf(mx0, fmaxf(s[t][0], s[t][1]));
            mx1 = fmaxf(mx1, fmaxf(s[t][2], s[t][3]));
        }
        mx0 = fmaxf(mx0, __shfl_xor_sync(0xffffffffu, mx0, 1));
        mx0 = fmaxf(mx0, __shfl_xor_sync(0xffffffffu, mx0, 2));
        mx1 = fmaxf(mx1, __shfl_xor_sync(0xffffffffu, mx1, 1));
        mx1 = fmaxf(mx1, __shfl_xor_sync(0xffffffffu, mx1, 2));

        float mn0 = fmaxf(m0, mx0), mn1 = fmaxf(m1, mx1);
        float a0 = __expf(m0 - mn0), a1 = __expf(m1 - mn1);
        m0 = mn0; m1 = mn1;

        // ---- P = exp(S - m); split to fp16 hi/lo in smem ----
        float rs0 = 0.f, rs1 = 0.f;
#pragma unroll
        for (int t = 0; t < 8; t++) {
            float p0 = __expf(s[t][0] - m0);
            float p1 = __expf(s[t][1] - m0);
            float p2 = __expf(s[t][2] - m1);
            float p3 = __expf(s[t][3] - m1);
            rs0 += p0 + p1; rs1 += p2 + p3;
            __half h0 = __float2half(p0), h1 = __float2half(p1);
            __half h2 = __float2half(p2), h3 = __float2half(p3);
            __half2 hp01 = {h0, h1}, hp23 = {h2, h3};
            __half2 lp01 = {__float2half(p0 - __half2float(h0)),
                            __float2half(p1 - __half2float(h1))};
            __half2 lp23 = {__float2half(p2 - __half2float(h2)),
                            __float2half(p3 - __half2float(h3))};
            uint32_t o0 = (uint32_t)(pr0 * 128 + (((t) ^ (pr0 & 7)) << 4) + (lane & 3) * 4);
            uint32_t o1 = (uint32_t)(pr1 * 128 + (((t) ^ (pr1 & 7)) << 4) + (lane & 3) * 4);
            *reinterpret_cast<__half2*>(smem + FA_PHI + o0) = hp01;
            *reinterpret_cast<__half2*>(smem + FA_PHI + o1) = hp23;
            *reinterpret_cast<__half2*>(smem + FA_PLO + o0) = lp01;
            *reinterpret_cast<__half2*>(smem + FA_PLO + o1) = lp23;
        }
        rs0 += __shfl_xor_sync(0xffffffffu, rs0, 1);
        rs0 += __shfl_xor_sync(0xffffffffu, rs0, 2);
        rs1 += __shfl_xor_sync(0xffffffffu, rs1, 1);
        rs1 += __shfl_xor_sync(0xffffffffu, rs1, 2);
        l0 = l0 * a0 + rs0;
        l1 = l1 * a1 + rs1;

#pragma unroll
        for (int g = 0; g < 16; g++) {
            o[g][0] *= a0; o[g][1] *= a0; o[g][2] *= a1; o[g][3] *= a1;
        }
        __syncwarp();

        // ---- O += (ph + pl) * v ----
        const int vrow0 = (lane & 7) + ((asel & 1) << 3);
        const int vkc   = asel >> 1;
#pragma unroll
        for (int ks = 0; ks < 4; ++ks) {
            uint32_t ph[4], pl[4];
            ldmatrix_x4(ph, su + FA_PHI + SW128(qrow_s, ks * 2 + akc));
            ldmatrix_x4(pl, su + FA_PLO + SW128(qrow_s, ks * 2 + akc));
            int vr = ks * 16 + vrow0;
#pragma unroll
            for (int g = 0; g < 8; ++g) {
                uint32_t vf[4];
                ldmatrix_x4_trans(vf, vb + SW256(vr, g * 2 + vkc));
                mma_fp16(o[2 * g],     ph, vf[0], vf[1]);
                mma_fp16(o[2 * g + 1], ph, vf[2], vf[3]);
                mma_fp16(o[2 * g],     pl, vf[0], vf[1]);
                mma_fp16(o[2 * g + 1], pl, vf[2], vf[3]);
            }
        }
        __syncthreads();
    }

    float inv0 = 1.0f / l0, inv1 = 1.0f / l1;
    int row0 = b * SEQ + q0 + wid * 16 + (lane >> 2);
    int row1 = row0 + 8;
#pragma unroll
    for (int g = 0; g < 16; g++) {
        int col = h * HDIM + g * 8 + (lane & 3) * 2;
        float y0 = o[g][0] * inv0, y1 = o[g][1] * inv0;
        float y2 = o[g][2] * inv1, y3 = o[g][3] * inv1;
        split_store2h(x2, x2 + 2048, (size_t)row0 * 4096 + col, y0, y1);
        split_store2h(x2, x2 + 2048, (size_t)row1 * 4096 + col, y2, y3);
    }
}

// ---------------------------------------------------------------------------
// Launch
// ---------------------------------------------------------------------------
extern "C" void kernel_launch(void* const* d_in, const int* in_sizes, int n_in,
                              void* d_out, int out_size)
{
    const float* x    = (const float*)d_in[0];
    const float* cosp = (const float*)d_in[1];
    const float* sinp = (const float*)d_in[2];
    const float* Wq   = (const float*)d_in[3];
    const float* Wk   = (const float*)d_in[4];
    const float* Wv   = (const float*)d_in[5];
    const float* Wo   = (const float*)d_in[6];
    const float* bo   = (const float*)d_in[7];
    float* out = (float*)d_out;

    __half *x2, *wqkv, *wo2, *qh, *ql, *kh, *vh;
    cudaGetSymbolAddress((void**)&x2,   g_x2);
    cudaGetSymbolAddress((void**)&wqkv, g_wqkv);
    cudaGetSymbolAddress((void**)&wo2,  g_wo2);
    cudaGetSymbolAddress((void**)&qh,   g_qh);
    cudaGetSymbolAddress((void**)&ql,   g_ql);
    cudaGetSymbolAddress((void**)&kh,   g_kh);
    cudaGetSymbolAddress((void**)&vh,   g_vh);

    cudaFuncSetAttribute(hgemm_kernel, cudaFuncAttributeMaxDynamicSharedMemorySize, HG_SMEM);
    cudaFuncSetAttribute(qkv_gemm_kernel, cudaFuncAttributeMaxDynamicSharedMemorySize, HG_SMEM);
    cudaFuncSetAttribute(flash_hmma_kernel, cudaFuncAttributeMaxDynamicSharedMemorySize, FA_SMEM);

    // prep (order keeps qkv_gemm as our 4th launch for ncu -s 5)
    tconv_qkv_kernel<<<dim3(64, 64, 3), dim3(32, 8)>>>(Wq, Wk, Wv, wqkv);
    split2048_kernel<<<MROWS * CDIM / 4 / 256, 256>>>(x, x2);
    tconv_wo_kernel<<<dim3(64, 64), dim3(32, 8)>>>(Wo, wo2);

    // Fused QKV projection + rmsnorm + rope (fp16 2-segment GEMM, 64x64 warps)
    qkv_gemm_kernel<<<dim3(3072 / 128, MROWS / 128), HG_THREADS, HG_SMEM>>>(
        x2, wqkv, cosp, sinp, qh, ql, kh, vh);

    // fp16 flash attention (writes fp16 split output into x2)
    dim3 ga(SEQ / 128, BATCH * NHEAD);
    flash_hmma_kernel<<<ga, 256, FA_SMEM>>>(qh, ql, kh, vh, x2);

    // output projection + bias (fp16 2-segment GEMM, 64x64 warps)
    hgemm_kernel<<<dim3(QW / 128, MROWS / 128), HG_THREADS, HG_SMEM>>>(x2, wo2, out, QW, bo);
}

// round 13
// speedup vs baseline: 1.0685x; 1.0685x over previous
#include <cuda_runtime.h>
#include <cuda_bf16.h>
#include <cuda_fp16.h>
#include <math.h>
#include <stdint.h>

// Problem constants
#define BATCH 2
#define SEQ   2048
#define CDIM  2048
#define NHEAD 16
#define NKV   4
#define HDIM  128
#define HALF  64
#define MROWS (BATCH*SEQ)          // 4096
#define QW    (NHEAD*HDIM)         // 2048
#define KW    (NKV*HDIM)           // 512

// ---------------------------------------------------------------------------
// Scratch (device globals; no allocations allowed)
// ---------------------------------------------------------------------------
__device__ __half g_x2  [4096 * 4096];            // 32 MB fp16 [hi|lo] (x; later attn-out)
__device__ __half g_wqkv[3072 * 2048];            // 12 MB packed [Wq|Wk|Wv]^T fp16
__device__ __half g_wo2 [2048 * 2048];            // 8 MB Wo^T fp16
__device__ __half g_qh[MROWS * QW];               // 16 MB fp16 q hi
__device__ __half g_ql[MROWS * QW];               // 16 MB fp16 q lo
__device__ __half g_kh[MROWS * KW];               // 4 MB fp16 k (single)
__device__ __half g_vh[MROWS * KW];               // 4 MB fp16 v (single)

// ---------------------------------------------------------------------------
// Baseline-PTX tensor-core helpers
// ---------------------------------------------------------------------------
__device__ __forceinline__ uint32_t smem_u32_of(const void* p) {
    uint32_t a;
    asm("{ .reg .u64 t; cvta.to.shared.u64 t, %1; cvt.u32.u64 %0, t; }" : "=r"(a) : "l"(p));
    return a;
}
__device__ __forceinline__ void cp_async16(uint32_t saddr, const void* gaddr) {
    asm volatile("cp.async.cg.shared.global [%0], [%1], 16;" :: "r"(saddr), "l"(gaddr));
}
__device__ __forceinline__ void cp_commit() {
    asm volatile("cp.async.commit_group;" ::: "memory");
}
__device__ __forceinline__ void cp_wait0() {
    asm volatile("cp.async.wait_group 0;" ::: "memory");
}
__device__ __forceinline__ void cp_wait1() {
    asm volatile("cp.async.wait_group 1;" ::: "memory");
}
__device__ __forceinline__ void ldmatrix_x4(uint32_t* r, uint32_t addr) {
    asm volatile("ldmatrix.sync.aligned.m8n8.x4.shared.b16 {%0,%1,%2,%3}, [%4];"
                 : "=r"(r[0]), "=r"(r[1]), "=r"(r[2]), "=r"(r[3]) : "r"(addr));
}
__device__ __forceinline__ void ldmatrix_x4_trans(uint32_t* r, uint32_t addr) {
    asm volatile("ldmatrix.sync.aligned.m8n8.x4.trans.shared.b16 {%0,%1,%2,%3}, [%4];"
                 : "=r"(r[0]), "=r"(r[1]), "=r"(r[2]), "=r"(r[3]) : "r"(addr));
}
__device__ __forceinline__ void mma_fp16(float* c, const uint32_t* a, uint32_t b0, uint32_t b1) {
    asm volatile(
        "mma.sync.aligned.m16n8k16.row.col.f32.f16.f16.f32 "
        "{%0,%1,%2,%3}, {%4,%5,%6,%7}, {%8,%9}, {%0,%1,%2,%3};"
        : "+f"(c[0]), "+f"(c[1]), "+f"(c[2]), "+f"(c[3])
        : "r"(a[0]), "r"(a[1]), "r"(a[2]), "r"(a[3]), "r"(b0), "r"(b1));
}

// swizzled smem offsets (16B chunks, XOR row&7)
#define SW256(r, c) ((uint32_t)((r) * 256 + (((c) ^ ((r) & 7)) << 4)))
#define SW128(r, c) ((uint32_t)((r) * 128 + (((c) ^ ((r) & 7)) << 4)))

// fp16 hi/lo split store of 2 consecutive values
__device__ __forceinline__ void split_store2h(__half* oh, __half* ol,
                                              size_t idx, float a, float b) {
    __half h0 = __float2half(a), h1 = __float2half(b);
    __half2 hp = {h0, h1};
    __half2 lp = {__float2half(a - __half2float(h0)),
                  __float2half(b - __half2float(h1))};
    *reinterpret_cast<__half2*>(oh + idx) = hp;
    *reinterpret_cast<__half2*>(ol + idx) = lp;
}
__device__ __forceinline__ void store2h(__half* o, size_t idx, float a, float b) {
    __half2 hp = {__float2half(a), __float2half(b)};
    *reinterpret_cast<__half2*>(o + idx) = hp;
}

// ===========================================================================
// fp16 GEMM core: 128x128 CTA tile, 8 warps (2x4), warp tile 64x32.
// NIT=32 k-chunks; each stage holds {A_hi 16K | A_lo 16K | B 16K} so the
// B tile is read from gmem AND smem once for both segments:
//   per warp-ks: 2 B-ldm + 4 Ah-ldm + 4 Al-ldm -> 32 MMAs (160 B/MMA).
// 2-stage pipeline, issue-after-barrier (safe), prefetch distance 1.
// ===========================================================================
#define HG_STAGE 49152
#define HG_SMEM  (2 * HG_STAGE)
#define HG_NIT   32

struct GemmFrag { float acc[4][4][4]; };

__device__ __forceinline__ void gemm_mainloop(
    const __half* __restrict__ A2, const __half* __restrict__ B,
    uint32_t su, int m0, int n0, GemmFrag& F)
{
    const int tid  = threadIdx.x;
    const int wid  = tid >> 5;
    const int lane = tid & 31;

    uint32_t smoff[4];
    const __half *gAh[4], *gAl[4], *gB[4];
#pragma unroll
    for (int i = 0; i < 4; i++) {
        int id = tid + i * 256;
        int r = id >> 3, c = id & 7;
        smoff[i] = (uint32_t)(r * 128 + ((c ^ (r & 7)) << 4));
        gAh[i] = A2 + (size_t)(m0 + r) * 4096 + c * 8;
        gAl[i] = gAh[i] + 2048;
        gB[i]  = B  + (size_t)(n0 + r) * 2048 + c * 8;
    }

    const int mwarp = (wid >> 2) * 64;
    const int nwarp = (wid & 3) * 32;

    const int asel = lane >> 3;
    const int arow = (lane & 7) + ((asel & 1) << 3);
    const int akc  = asel >> 1;
    const int brow = (lane & 7) + ((asel >> 1) << 3);
    const int bkc  = asel & 1;

#pragma unroll
    for (int mf = 0; mf < 4; mf++)
#pragma unroll
        for (int nf = 0; nf < 4; nf++)
#pragma unroll
            for (int e = 0; e < 4; e++) F.acc[mf][nf][e] = 0.f;

    auto issue = [&](int t, int stage) {
        int koff = t * 64;
        uint32_t ah = su + (uint32_t)stage * (uint32_t)HG_STAGE;
        uint32_t al = ah + 16384u;
        uint32_t bb = ah + 32768u;
#pragma unroll
        for (int i = 0; i < 4; i++) {
            cp_async16(ah + smoff[i], gAh[i] + koff);
            cp_async16(al + smoff[i], gAl[i] + koff);
            cp_async16(bb + smoff[i], gB[i]  + koff);
        }
        cp_commit();
    };

    issue(0, 0);
    for (int it = 0; it < HG_NIT; ++it) {
        cp_wait0();
        __syncthreads();
        if (it + 1 < HG_NIT) issue(it + 1, (it + 1) & 1);

        uint32_t ahb = su + (uint32_t)(it & 1) * (uint32_t)HG_STAGE;
        uint32_t alb = ahb + 16384u;
        uint32_t bbb = ahb + 32768u;

#pragma unroll
        for (int ks = 0; ks < 4; ++ks) {
            uint32_t br[2][4];
#pragma unroll
            for (int bh = 0; bh < 2; bh++) {
                int R = nwarp + bh * 16 + brow;
                int ch = ks * 2 + bkc;
                ldmatrix_x4(br[bh], bbb + R * 128 + (uint32_t)((ch ^ (R & 7)) << 4));
            }
#pragma unroll
            for (int mf = 0; mf < 4; mf++) {
                int R = mwarp + mf * 16 + arow;
                uint32_t off = (uint32_t)(R * 128 + (((ks * 2 + akc) ^ (R & 7)) << 4));
                uint32_t ah[4], al[4];
                ldmatrix_x4(ah, ahb + off);
                ldmatrix_x4(al, alb + off);
                mma_fp16(F.acc[mf][0], ah, br[0][0], br[0][1]);
                mma_fp16(F.acc[mf][1], ah, br[0][2], br[0][3]);
                mma_fp16(F.acc[mf][2], ah, br[1][0], br[1][1]);
                mma_fp16(F.acc[mf][3], ah, br[1][2], br[1][3]);
                mma_fp16(F.acc[mf][0], al, br[0][0], br[0][1]);
                mma_fp16(F.acc[mf][1], al, br[0][2], br[0][3]);
                mma_fp16(F.acc[mf][2], al, br[1][0], br[1][1]);
                mma_fp16(F.acc[mf][3], al, br[1][2], br[1][3]);
            }
        }
    }
}

// ---------------------------------------------------------------------------
// Generic GEMM with fp32 output + optional bias (used for Wo).
// ---------------------------------------------------------------------------
__global__ __launch_bounds__(256, 2)
void hgemm_kernel(const __half* __restrict__ A2, const __half* __restrict__ B,
                  float* __restrict__ C, int N, const float* __restrict__ bias)
{
    extern __shared__ __align__(1024) char smem[];
    const uint32_t su = smem_u32_of(smem);
    const int tid  = threadIdx.x;
    const int wid  = tid >> 5;
    const int lane = tid & 31;
    const int m0 = blockIdx.y * 128;
    const int n0 = blockIdx.x * 128;

    GemmFrag F;
    gemm_mainloop(A2, B, su, m0, n0, F);

    const int mwarp = (wid >> 2) * 64;
    const int nwarp = (wid & 3) * 32;
    const int mrow = lane >> 2;
    const int ncol = (lane & 3) * 2;
#pragma unroll
    for (int mf = 0; mf < 4; mf++) {
#pragma unroll
        for (int nf = 0; nf < 4; nf++) {
            int gm = m0 + mwarp + mf * 16 + mrow;
            int gn = n0 + nwarp + nf * 8 + ncol;
            float b0 = 0.f, b1 = 0.f;
            if (bias != nullptr) { b0 = bias[gn]; b1 = bias[gn + 1]; }
            float2 lo = make_float2(F.acc[mf][nf][0] + b0, F.acc[mf][nf][1] + b1);
            float2 hi = make_float2(F.acc[mf][nf][2] + b0, F.acc[mf][nf][3] + b1);
            *reinterpret_cast<float2*>(C + (size_t)gm * N + gn)       = lo;
            *reinterpret_cast<float2*>(C + (size_t)(gm + 8) * N + gn) = hi;
        }
    }
}

// ---------------------------------------------------------------------------
// Fused QKV GEMM + per-head RMSNorm + RoPE + fp16 epilogue.
//   cols [0,2048)    -> q heads: rmsnorm+rope -> qh/ql (fp16 hi/lo)
//   cols [2048,2560) -> k heads: rmsnorm+rope -> kh (fp16 single)
//   cols [2560,3072) -> v: fp16 single -> vh
// ---------------------------------------------------------------------------
__global__ __launch_bounds__(256, 2)
void qkv_gemm_kernel(const __half* __restrict__ A2, const __half* __restrict__ B,
                     const float* __restrict__ cosp, const float* __restrict__ sinp,
                     __half* __restrict__ qh, __half* __restrict__ ql,
                     __half* __restrict__ kh, __half* __restrict__ vh)
{
    extern __shared__ __align__(1024) char smem[];
    const uint32_t su = smem_u32_of(smem);
    const int tid  = threadIdx.x;
    const int wid  = tid >> 5;
    const int lane = tid & 31;
    const int m0 = blockIdx.y * 128;
    const int n0 = blockIdx.x * 128;

    GemmFrag F;
    gemm_mainloop(A2, B, su, m0, n0, F);

    const int mwarp = (wid >> 2) * 64;
    const int nwarp = (wid & 3) * 32;
    const int mrow = lane >> 2;
    const int ncol = (lane & 3) * 2;

    if (n0 >= 2560) {
        // V region: single fp16
#pragma unroll
        for (int mf = 0; mf < 4; mf++)
#pragma unroll
            for (int nf = 0; nf < 4; nf++) {
                int gm = m0 + mwarp + mf * 16 + mrow;
                int gn = n0 - 2560 + nwarp + nf * 8 + ncol;
                store2h(vh, (size_t)gm * 512 + gn,       F.acc[mf][nf][0], F.acc[mf][nf][1]);
                store2h(vh, (size_t)(gm + 8) * 512 + gn, F.acc[mf][nf][2], F.acc[mf][nf][3]);
            }
        return;
    }

    // ---- Q/K region: RMSNorm + RoPE, all in-CTA ----
    __syncthreads();   // pipeline smem no longer needed; safe to reuse
    const int NP = 132;
    float* ntile = reinterpret_cast<float*>(smem);     // [128][132] fp32
    float* ssqp  = ntile + 128 * NP;                   // [4][128]
    float* rmsv  = ssqp + 512;                         // [128]

#pragma unroll
    for (int mf = 0; mf < 4; mf++) {
        int lr0 = mwarp + mf * 16 + mrow;
        int lr1 = lr0 + 8;
        float p0 = 0.f, p1 = 0.f;
#pragma unroll
        for (int nf = 0; nf < 4; nf++) {
            int cc = nwarp + nf * 8 + ncol;
            float a0 = F.acc[mf][nf][0], a1 = F.acc[mf][nf][1];
            float a2 = F.acc[mf][nf][2], a3 = F.acc[mf][nf][3];
            ntile[lr0 * NP + cc]     = a0;
            ntile[lr0 * NP + cc + 1] = a1;
            ntile[lr1 * NP + cc]     = a2;
            ntile[lr1 * NP + cc + 1] = a3;
            p0 += a0 * a0 + a1 * a1;
            p1 += a2 * a2 + a3 * a3;
        }
        p0 += __shfl_xor_sync(0xffffffffu, p0, 1);
        p0 += __shfl_xor_sync(0xffffffffu, p0, 2);
        p1 += __shfl_xor_sync(0xffffffffu, p1, 1);
        p1 += __shfl_xor_sync(0xffffffffu, p1, 2);
        if ((lane & 3) == 0) {
            ssqp[(wid & 3) * 128 + lr0] = p0;
            ssqp[(wid & 3) * 128 + lr1] = p1;
        }
    }
    __syncthreads();
    if (tid < 128) {
        float s = ssqp[tid] + ssqp[128 + tid] + ssqp[256 + tid] + ssqp[384 + tid];
        rmsv[tid] = rsqrtf(s * (1.0f / 128.0f) + 1.1920929e-7f);
    }
    __syncthreads();

    // RoPE + store: 2 threads per row, 32 dims each half
    {
        int r = tid >> 1;
        int dbase = (tid & 1) * 32;
        int gm = m0 + r;
        int t  = gm & (SEQ - 1);
        float rm = rmsv[r];
        const bool isq = (n0 < 2048);
        size_t stride = isq ? 2048 : 512;
        int colbase = isq ? n0 : (n0 - 2048);
        size_t rowoff = (size_t)gm * stride + colbase;
        const float* crow = cosp + t * HALF;
        const float* srow = sinp + t * HALF;
        const float* nrow = ntile + r * NP;
#pragma unroll 4
        for (int j = 0; j < 32; j += 2) {
            int d = dbase + j;
            float v0a = nrow[d]      * rm, v1a = nrow[d + 64] * rm;
            float v0b = nrow[d + 1]  * rm, v1b = nrow[d + 65] * rm;
            float ca = crow[d],     sa = srow[d];
            float cb = crow[d + 1], sb = srow[d + 1];
            float y0 = v0a * ca - v1a * sa, y1 = v0b * cb - v1b * sb;
            float y2 = v0a * sa + v1a * ca, y3 = v0b * sb + v1b * cb;
            if (isq) {
                split_store2h(qh, ql, rowoff + d,      y0, y1);
                split_store2h(qh, ql, rowoff + 64 + d, y2, y3);
            } else {
                store2h(kh, rowoff + d,      y0, y1);
                store2h(kh, rowoff + 64 + d, y2, y3);
            }
        }
    }
}

// ---------------------------------------------------------------------------
// fp32 -> (hi, lo) fp16 split. src [M, 2048] -> dst [M, 4096] ([hi|lo]).
// ---------------------------------------------------------------------------
__global__ void split2048_kernel(const float* __restrict__ src, __half* __restrict__ dst)
{
    int i = blockIdx.x * 256 + threadIdx.x;
    float4 v = reinterpret_cast<const float4*>(src)[i];
    int e = i * 4;
    int m = e >> 11;
    int k = e & 2047;
    __half* d = dst + (size_t)m * 4096 + k;
    __half h0 = __float2half(v.x), h1 = __float2half(v.y);
    __half h2 = __float2half(v.z), h3 = __float2half(v.w);
    d[0] = h0; d[1] = h1; d[2] = h2; d[3] = h3;
    d[2048] = __float2half(v.x - __half2float(h0));
    d[2049] = __float2half(v.y - __half2float(h1));
    d[2050] = __float2half(v.z - __half2float(h2));
    d[2051] = __float2half(v.w - __half2float(h3));
}

// ---------------------------------------------------------------------------
// Transposed fp16 convert of W [2048, N] into dst columns [nbase, nbase+N),
// K-major [n][2048].
// ---------------------------------------------------------------------------
__device__ __forceinline__ void tconv_body(const float* __restrict__ W,
                                           __half* __restrict__ dst,
                                           int N, int nbase, int bx, int by)
{
    __shared__ float tl[32][33];
    int tx = threadIdx.x, ty = threadIdx.y;
    int n0 = bx * 32, k0 = by * 32;
#pragma unroll
    for (int j = 0; j < 4; j++)
        tl[ty + j * 8][tx] = W[(size_t)(k0 + ty + j * 8) * N + n0 + tx];
    __syncthreads();
#pragma unroll
    for (int j = 0; j < 4; j++) {
        int n = nbase + n0 + ty + j * 8;
        int k = k0 + tx;
        dst[(size_t)n * 2048 + k] = __float2half(tl[tx][ty + j * 8]);
    }
}

__global__ void tconv_qkv_kernel(const float* __restrict__ Wq, const float* __restrict__ Wk,
                                 const float* __restrict__ Wv, __half* __restrict__ dst)
{
    int z = blockIdx.z;
    const float* W = (z == 0) ? Wq : (z == 1) ? Wk : Wv;
    int N     = (z == 0) ? 2048 : 512;
    int nbase = (z == 0) ? 0 : (z == 1) ? 2048 : 2560;
    if ((int)blockIdx.x * 32 >= N) return;
    tconv_body(W, dst, N, nbase, blockIdx.x, blockIdx.y);
}

__global__ void tconv_wo_kernel(const float* __restrict__ W, __half* __restrict__ dst)
{
    tconv_body(W, dst, 2048, 0, blockIdx.x, blockIdx.y);
}

// ---------------------------------------------------------------------------
// fp16 HMMA flash attention, causal, GQA (unchanged from round 11).
//   S = qh*k + ql*k (2 terms).  O += ph*v + pl*v (2 terms).
// ---------------------------------------------------------------------------
#define FA_QHI 0
#define FA_QLO 32768
#define FA_K   65536
#define FA_V   98304
#define FA_PHI 131072
#define FA_PLO 147456
#define FA_SMEM 163840

__global__ __launch_bounds__(256, 1)
void flash_hmma_kernel(const __half* __restrict__ qh, const __half* __restrict__ ql,
                       const __half* __restrict__ kh, const __half* __restrict__ vh,
                       __half* __restrict__ x2)
{
    extern __shared__ __align__(1024) char smem[];
    const uint32_t su = smem_u32_of(smem);
    const int tid  = threadIdx.x;
    const int wid  = tid >> 5;
    const int lane = tid & 31;

    const int qt = (int)gridDim.x - 1 - (int)blockIdx.x;   // long CTAs first
    const int bh = blockIdx.y;
    const int b  = bh >> 4;
    const int h  = bh & 15;
    const int hkv = h >> 2;
    const int q0 = qt * 128;
    const float scale = 0.08838834764831845f;   // 1/sqrt(128)

    const __half* qhb = qh + (size_t)b * SEQ * QW + h * HDIM;
    const __half* qlb = ql + (size_t)b * SEQ * QW + h * HDIM;
    const __half* khb = kh + (size_t)b * SEQ * KW + hkv * HDIM;
    const __half* vhb = vh + (size_t)b * SEQ * KW + hkv * HDIM;

    for (int i = tid; i < 128 * 16; i += 256) {
        int r = i >> 4, c = i & 15;
        *reinterpret_cast<uint4*>(smem + FA_QHI + SW256(r, c)) =
            *reinterpret_cast<const uint4*>(qhb + (size_t)(q0 + r) * QW + c * 8);
        *reinterpret_cast<uint4*>(smem + FA_QLO + SW256(r, c)) =
            *reinterpret_cast<const uint4*>(qlb + (size_t)(q0 + r) * QW + c * 8);
    }

    const int asel = lane >> 3;
    const int arow = (lane & 7) + ((asel & 1) << 3);
    const int akc  = asel >> 1;
    const int brow = (lane & 7) + ((asel >> 1) << 3);
    const int bkc  = asel & 1;
    const int qrow_s = wid * 16 + arow;

    float o[16][4];
#pragma unroll
    for (int g = 0; g < 16; g++)
#pragma unroll
        for (int e = 0; e < 4; e++) o[g][e] = 0.f;
    float m0 = -1e30f, m1 = -1e30f, l0 = 0.f, l1 = 0.f;

    const int ntiles = 2 * qt + 2;

    auto issueKV = [&](int kt) {
        int k0 = kt * 64;
        uint32_t kb = su + FA_K + (uint32_t)(kt & 1) * 16384u;
        uint32_t vb = su + FA_V + (uint32_t)(kt & 1) * 16384u;
#pragma unroll
        for (int i = 0; i < 4; i++) {
            int id = tid + i * 256;
            int r = id >> 4, c = id & 15;
            size_t go = (size_t)(k0 + r) * KW + c * 8;
            uint32_t so = SW256(r, c);
            cp_async16(kb + so, khb + go);
            cp_async16(vb + so, vhb + go);
        }
        cp_commit();
    };

    issueKV(0);

    const int r0g = q0 + wid * 16 + (lane >> 2);
    const int r1g = r0g + 8;
    const int pr0 = wid * 16 + (lane >> 2);
    const int pr1 = pr0 + 8;

    for (int kt = 0; kt < ntiles; ++kt) {
        if (kt + 1 < ntiles) { issueKV(kt + 1); cp_wait1(); }
        else                 { cp_wait0(); }
        __syncthreads();

        uint32_t kb = su + FA_K + (uint32_t)(kt & 1) * 16384u;
        uint32_t vb = su + FA_V + (uint32_t)(kt & 1) * 16384u;

        // ---- S = QK^T (fp16, 2 terms) ----
        float s[8][4];
#pragma unroll
        for (int t = 0; t < 8; t++)
#pragma unroll
            for (int e = 0; e < 4; e++) s[t][e] = 0.f;

#pragma unroll
        for (int d = 0; d < 8; ++d) {
            uint32_t ah[4], al[4];
            ldmatrix_x4(ah, su + FA_QHI + SW256(qrow_s, d * 2 + akc));
            ldmatrix_x4(al, su + FA_QLO + SW256(qrow_s, d * 2 + akc));
#pragma unroll
            for (int j = 0; j < 4; ++j) {
                int R = j * 16 + brow;
                uint32_t kf[4];
                ldmatrix_x4(kf, kb + SW256(R, d * 2 + bkc));
                mma_fp16(s[2 * j],     ah, kf[0], kf[1]);
                mma_fp16(s[2 * j + 1], ah, kf[2], kf[3]);
                mma_fp16(s[2 * j],     al, kf[0], kf[1]);
                mma_fp16(s[2 * j + 1], al, kf[2], kf[3]);
            }
        }

        const int k0 = kt * 64;
        const bool dm = (kt >= 2 * qt);
        float mx0 = -1e30f, mx1 = -1e30f;
#pragma unroll
        for (int t = 0; t < 8; t++) {
            int c0 = k0 + t * 8 + (lane & 3) * 2;
            s[t][0] *= scale; s[t][1] *= scale; s[t][2] *= scale; s[t][3] *= scale;
            if (dm) {
                if (c0     > r0g) s[t][0] = -1e30f;
                if (c0 + 1 > r0g) s[t][1] = -1e30f;
                if (c0     > r1g) s[t][2] = -1e30f;
                if (c0 + 1 > r1g) s[t][3] = -1e30f;
            }
            mx0 = fmaxf(mx0, fmaxf(s[t][0], s[t][1]));
            mx1 = fmaxf(mx1, fmaxf(s[t][2], s[t][3]));
        }
        mx0 = fmaxf(mx0, __shfl_xor_sync(0xffffffffu, mx0, 1));
        mx0 = fmaxf(mx0, __shfl_xor_sync(0xffffffffu, mx0, 2));
        mx1 = fmaxf(mx1, __shfl_xor_sync(0xffffffffu, mx1, 1));
        mx1 = fmaxf(mx1, __shfl_xor_sync(0xffffffffu, mx1, 2));

        float mn0 = fmaxf(m0, mx0), mn1 = fmaxf(m1, mx1);
        float a0 = __expf(m0 - mn0), a1 = __expf(m1 - mn1);
        m0 = mn0; m1 = mn1;

        // ---- P = exp(S - m); split to fp16 hi/lo in smem ----
        float rs0 = 0.f, rs1 = 0.f;
#pragma unroll
        for (int t = 0; t < 8; t++) {
            float p0 = __expf(s[t][0] - m0);
            float p1 = __expf(s[t][1] - m0);
            float p2 = __expf(s[t][2] - m1);
            float p3 = __expf(s[t][3] - m1);
            rs0 += p0 + p1; rs1 += p2 + p3;
            __half h0 = __float2half(p0), h1 = __float2half(p1);
            __half h2 = __float2half(p2), h3 = __float2half(p3);
            __half2 hp01 = {h0, h1}, hp23 = {h2, h3};
            __half2 lp01 = {__float2half(p0 - __half2float(h0)),
                            __float2half(p1 - __half2float(h1))};
            __half2 lp23 = {__float2half(p2 - __half2float(h2)),
                            __float2half(p3 - __half2float(h3))};
            uint32_t o0 = (uint32_t)(pr0 * 128 + (((t) ^ (pr0 & 7)) << 4) + (lane & 3) * 4);
            uint32_t o1 = (uint32_t)(pr1 * 128 + (((t) ^ (pr1 & 7)) << 4) + (lane & 3) * 4);
            *reinterpret_cast<__half2*>(smem + FA_PHI + o0) = hp01;
            *reinterpret_cast<__half2*>(smem + FA_PHI + o1) = hp23;
            *reinterpret_cast<__half2*>(smem + FA_PLO + o0) = lp01;
            *reinterpret_cast<__half2*>(smem + FA_PLO + o1) = lp23;
        }
        rs0 += __shfl_xor_sync(0xffffffffu, rs0, 1);
        rs0 += __shfl_xor_sync(0xffffffffu, rs0, 2);
        rs1 += __shfl_xor_sync(0xffffffffu, rs1, 1);
        rs1 += __shfl_xor_sync(0xffffffffu, rs1, 2);
        l0 = l0 * a0 + rs0;
        l1 = l1 * a1 + rs1;

#pragma unroll
        for (int g = 0; g < 16; g++) {
            o[g][0] *= a0; o[g][1] *= a0; o[g][2] *= a1; o[g][3] *= a1;
        }
        __syncwarp();

        // ---- O += (ph + pl) * v ----
        const int vrow0 = (lane & 7) + ((asel & 1) << 3);
        const int vkc   = asel >> 1;
#pragma unroll
        for (int ks = 0; ks < 4; ++ks) {
            uint32_t ph[4], pl[4];
            ldmatrix_x4(ph, su + FA_PHI + SW128(qrow_s, ks * 2 + akc));
            ldmatrix_x4(pl, su + FA_PLO + SW128(qrow_s, ks * 2 + akc));
            int vr = ks * 16 + vrow0;
#pragma unroll
            for (int g = 0; g < 8; ++g) {
                uint32_t vf[4];
                ldmatrix_x4_trans(vf, vb + SW256(vr, g * 2 + vkc));
                mma_fp16(o[2 * g],     ph, vf[0], vf[1]);
                mma_fp16(o[2 * g + 1], ph, vf[2], vf[3]);
                mma_fp16(o[2 * g],     pl, vf[0], vf[1]);
                mma_fp16(o[2 * g + 1], pl, vf[2], vf[3]);
            }
        }
        __syncthreads();
    }

    float inv0 = 1.0f / l0, inv1 = 1.0f / l1;
    int row0 = b * SEQ + q0 + wid * 16 + (lane >> 2);
    int row1 = row0 + 8;
#pragma unroll
    for (int g = 0; g < 16; g++) {
        int col = h * HDIM + g * 8 + (lane & 3) * 2;
        float y0 = o[g][0] * inv0, y1 = o[g][1] * inv0;
        float y2 = o[g][2] * inv1, y3 = o[g][3] * inv1;
        split_store2h(x2, x2 + 2048, (size_t)row0 * 4096 + col, y0, y1);
        split_store2h(x2, x2 + 2048, (size_t)row1 * 4096 + col, y2, y3);
    }
}

// ---------------------------------------------------------------------------
// Launch
// ---------------------------------------------------------------------------
extern "C" void kernel_launch(void* const* d_in, const int* in_sizes, int n_in,
                              void* d_out, int out_size)
{
    const float* x    = (const float*)d_in[0];
    const float* cosp = (const float*)d_in[1];
    const float* sinp = (const float*)d_in[2];
    const float* Wq   = (const float*)d_in[3];
    const float* Wk   = (const float*)d_in[4];
    const float* Wv   = (const float*)d_in[5];
    const float* Wo   = (const float*)d_in[6];
    const float* bo   = (const float*)d_in[7];
    float* out = (float*)d_out;

    __half *x2, *wqkv, *wo2, *qh, *ql, *kh, *vh;
    cudaGetSymbolAddress((void**)&x2,   g_x2);
    cudaGetSymbolAddress((void**)&wqkv, g_wqkv);
    cudaGetSymbolAddress((void**)&wo2,  g_wo2);
    cudaGetSymbolAddress((void**)&qh,   g_qh);
    cudaGetSymbolAddress((void**)&ql,   g_ql);
    cudaGetSymbolAddress((void**)&kh,   g_kh);
    cudaGetSymbolAddress((void**)&vh,   g_vh);

    cudaFuncSetAttribute(hgemm_kernel, cudaFuncAttributeMaxDynamicSharedMemorySize, HG_SMEM);
    cudaFuncSetAttribute(qkv_gemm_kernel, cudaFuncAttributeMaxDynamicSharedMemorySize, HG_SMEM);
    cudaFuncSetAttribute(flash_hmma_kernel, cudaFuncAttributeMaxDynamicSharedMemorySize, FA_SMEM);

    // prep (order keeps qkv_gemm as our 4th launch for ncu -s 5)
    tconv_qkv_kernel<<<dim3(64, 64, 3), dim3(32, 8)>>>(Wq, Wk, Wv, wqkv);
    split2048_kernel<<<MROWS * CDIM / 4 / 256, 256>>>(x, x2);
    tconv_wo_kernel<<<dim3(64, 64), dim3(32, 8)>>>(Wo, wo2);

    // Fused QKV projection + rmsnorm + rope (fp16 2-segment GEMM, shared-B loop)
    qkv_gemm_kernel<<<dim3(3072 / 128, MROWS / 128), 256, HG_SMEM>>>(
        x2, wqkv, cosp, sinp, qh, ql, kh, vh);

    // fp16 flash attention (writes fp16 split output into x2)
    dim3 ga(SEQ / 128, BATCH * NHEAD);
    flash_hmma_kernel<<<ga, 256, FA_SMEM>>>(qh, ql, kh, vh, x2);

    // output projection + bias (fp16 2-segment GEMM, shared-B loop)
    hgemm_kernel<<<dim3(QW / 128, MROWS / 128), 256, HG_SMEM>>>(x2, wo2, out, QW, bo);
}

// round 14
// speedup vs baseline: 1.0719x; 1.0032x over previous
#include <cuda_runtime.h>
#include <cuda_bf16.h>
#include <cuda_fp16.h>
#include <math.h>
#include <stdint.h>

// Problem constants
#define BATCH 2
#define SEQ   2048
#define CDIM  2048
#define NHEAD 16
#define NKV   4
#define HDIM  128
#define HALF  64
#define MROWS (BATCH*SEQ)          // 4096
#define QW    (NHEAD*HDIM)         // 2048
#define KW    (NKV*HDIM)           // 512

// ---------------------------------------------------------------------------
// Scratch (device globals; no allocations allowed)
// ---------------------------------------------------------------------------
__device__ __half g_x2  [4096 * 4096];            // 32 MB fp16 [hi|lo] (x; later attn-out)
__device__ __half g_wqkv[3072 * 2048];            // 12 MB packed [Wq|Wk|Wv]^T fp16
__device__ __half g_wo2 [2048 * 2048];            // 8 MB Wo^T fp16
__device__ __half g_qh[MROWS * QW];               // 16 MB fp16 q hi
__device__ __half g_ql[MROWS * QW];               // 16 MB fp16 q lo
__device__ __half g_kh[MROWS * KW];               // 4 MB fp16 k (single)
__device__ __half g_vh[MROWS * KW];               // 4 MB fp16 v (single)

// ---------------------------------------------------------------------------
// Baseline-PTX tensor-core helpers
// ---------------------------------------------------------------------------
__device__ __forceinline__ uint32_t smem_u32_of(const void* p) {
    uint32_t a;
    asm("{ .reg .u64 t; cvta.to.shared.u64 t, %1; cvt.u32.u64 %0, t; }" : "=r"(a) : "l"(p));
    return a;
}
__device__ __forceinline__ void cp_async16(uint32_t saddr, const void* gaddr) {
    asm volatile("cp.async.cg.shared.global [%0], [%1], 16;" :: "r"(saddr), "l"(gaddr));
}
__device__ __forceinline__ void cp_commit() {
    asm volatile("cp.async.commit_group;" ::: "memory");
}
__device__ __forceinline__ void cp_wait0() {
    asm volatile("cp.async.wait_group 0;" ::: "memory");
}
__device__ __forceinline__ void cp_wait1() {
    asm volatile("cp.async.wait_group 1;" ::: "memory");
}
__device__ __forceinline__ void ldmatrix_x4(uint32_t* r, uint32_t addr) {
    asm volatile("ldmatrix.sync.aligned.m8n8.x4.shared.b16 {%0,%1,%2,%3}, [%4];"
                 : "=r"(r[0]), "=r"(r[1]), "=r"(r[2]), "=r"(r[3]) : "r"(addr));
}
__device__ __forceinline__ void ldmatrix_x4_trans(uint32_t* r, uint32_t addr) {
    asm volatile("ldmatrix.sync.aligned.m8n8.x4.trans.shared.b16 {%0,%1,%2,%3}, [%4];"
                 : "=r"(r[0]), "=r"(r[1]), "=r"(r[2]), "=r"(r[3]) : "r"(addr));
}
__device__ __forceinline__ void mma_fp16(float* c, const uint32_t* a, uint32_t b0, uint32_t b1) {
    asm volatile(
        "mma.sync.aligned.m16n8k16.row.col.f32.f16.f16.f32 "
        "{%0,%1,%2,%3}, {%4,%5,%6,%7}, {%8,%9}, {%0,%1,%2,%3};"
        : "+f"(c[0]), "+f"(c[1]), "+f"(c[2]), "+f"(c[3])
        : "r"(a[0]), "r"(a[1]), "r"(a[2]), "r"(a[3]), "r"(b0), "r"(b1));
}

// swizzled smem offsets (16B chunks, XOR row&7)
#define SW256(r, c) ((uint32_t)((r) * 256 + (((c) ^ ((r) & 7)) << 4)))
#define SW128(r, c) ((uint32_t)((r) * 128 + (((c) ^ ((r) & 7)) << 4)))

// fp16 hi/lo split store of 2 consecutive values
__device__ __forceinline__ void split_store2h(__half* oh, __half* ol,
                                              size_t idx, float a, float b) {
    __half h0 = __float2half(a), h1 = __float2half(b);
    __half2 hp = {h0, h1};
    __half2 lp = {__float2half(a - __half2float(h0)),
                  __float2half(b - __half2float(h1))};
    *reinterpret_cast<__half2*>(oh + idx) = hp;
    *reinterpret_cast<__half2*>(ol + idx) = lp;
}
__device__ __forceinline__ void store2h(__half* o, size_t idx, float a, float b) {
    __half2 hp = {__float2half(a), __float2half(b)};
    *reinterpret_cast<__half2*>(o + idx) = hp;
}

// ===========================================================================
// fp16 GEMM core: 128x128 CTA tile, 8 warps (4x2), warp tile 32x64.
// NIT=32 k-chunks; each stage holds {A_hi 16K | A_lo 16K | B 16K}.
// Per warp-ks: 4 B-ldm + 2 Ah-ldm + 2 Al-ldm -> 32 MMAs (128 B/MMA).
// 2-stage pipeline, issue-after-barrier, prefetch distance 1.
// ===========================================================================
#define HG_STAGE 49152
#define HG_SMEM  (2 * HG_STAGE)
#define HG_NIT   32

struct GemmFrag { float acc[2][8][4]; };

__device__ __forceinline__ void gemm_mainloop(
    const __half* __restrict__ A2, const __half* __restrict__ B,
    uint32_t su, int m0, int n0, GemmFrag& F)
{
    const int tid  = threadIdx.x;
    const int wid  = tid >> 5;
    const int lane = tid & 31;

    uint32_t smoff[4];
    const __half *gAh[4], *gAl[4], *gB[4];
#pragma unroll
    for (int i = 0; i < 4; i++) {
        int id = tid + i * 256;
        int r = id >> 3, c = id & 7;
        smoff[i] = (uint32_t)(r * 128 + ((c ^ (r & 7)) << 4));
        gAh[i] = A2 + (size_t)(m0 + r) * 4096 + c * 8;
        gAl[i] = gAh[i] + 2048;
        gB[i]  = B  + (size_t)(n0 + r) * 2048 + c * 8;
    }

    const int mwarp = (wid & 3) * 32;
    const int nwarp = (wid >> 2) * 64;

    const int asel = lane >> 3;
    const int arow = (lane & 7) + ((asel & 1) << 3);
    const int akc  = asel >> 1;
    const int brow = (lane & 7) + ((asel >> 1) << 3);
    const int bkc  = asel & 1;

#pragma unroll
    for (int mf = 0; mf < 2; mf++)
#pragma unroll
        for (int nf = 0; nf < 8; nf++)
#pragma unroll
            for (int e = 0; e < 4; e++) F.acc[mf][nf][e] = 0.f;

    auto issue = [&](int t, int stage) {
        int koff = t * 64;
        uint32_t ah = su + (uint32_t)stage * (uint32_t)HG_STAGE;
        uint32_t al = ah + 16384u;
        uint32_t bb = ah + 32768u;
#pragma unroll
        for (int i = 0; i < 4; i++) {
            cp_async16(ah + smoff[i], gAh[i] + koff);
            cp_async16(al + smoff[i], gAl[i] + koff);
            cp_async16(bb + smoff[i], gB[i]  + koff);
        }
        cp_commit();
    };

    issue(0, 0);
    for (int it = 0; it < HG_NIT; ++it) {
        cp_wait0();
        __syncthreads();
        if (it + 1 < HG_NIT) issue(it + 1, (it + 1) & 1);

        uint32_t ahb = su + (uint32_t)(it & 1) * (uint32_t)HG_STAGE;
        uint32_t alb = ahb + 16384u;
        uint32_t bbb = ahb + 32768u;

#pragma unroll
        for (int ks = 0; ks < 4; ++ks) {
            uint32_t br[4][4];
#pragma unroll
            for (int bh = 0; bh < 4; bh++) {
                int R = nwarp + bh * 16 + brow;
                int ch = ks * 2 + bkc;
                ldmatrix_x4(br[bh], bbb + R * 128 + (uint32_t)((ch ^ (R & 7)) << 4));
            }
#pragma unroll
            for (int mf = 0; mf < 2; mf++) {
                int R = mwarp + mf * 16 + arow;
                uint32_t off = (uint32_t)(R * 128 + (((ks * 2 + akc) ^ (R & 7)) << 4));
                uint32_t ah[4], al[4];
                ldmatrix_x4(ah, ahb + off);
                ldmatrix_x4(al, alb + off);
#pragma unroll
                for (int bh = 0; bh < 4; bh++) {
                    mma_fp16(F.acc[mf][2 * bh],     ah, br[bh][0], br[bh][1]);
                    mma_fp16(F.acc[mf][2 * bh + 1], ah, br[bh][2], br[bh][3]);
                }
#pragma unroll
                for (int bh = 0; bh < 4; bh++) {
                    mma_fp16(F.acc[mf][2 * bh],     al, br[bh][0], br[bh][1]);
                    mma_fp16(F.acc[mf][2 * bh + 1], al, br[bh][2], br[bh][3]);
                }
            }
        }
    }
}

// ---------------------------------------------------------------------------
// Generic GEMM with fp32 output + optional bias (used for Wo).
// ---------------------------------------------------------------------------
__global__ __launch_bounds__(256, 2)
void hgemm_kernel(const __half* __restrict__ A2, const __half* __restrict__ B,
                  float* __restrict__ C, int N, const float* __restrict__ bias)
{
    extern __shared__ __align__(1024) char smem[];
    const uint32_t su = smem_u32_of(smem);
    const int tid  = threadIdx.x;
    const int wid  = tid >> 5;
    const int lane = tid & 31;
    const int m0 = blockIdx.y * 128;
    const int n0 = blockIdx.x * 128;

    GemmFrag F;
    gemm_mainloop(A2, B, su, m0, n0, F);

    const int mwarp = (wid & 3) * 32;
    const int nwarp = (wid >> 2) * 64;
    const int mrow = lane >> 2;
    const int ncol = (lane & 3) * 2;
#pragma unroll
    for (int mf = 0; mf < 2; mf++) {
#pragma unroll
        for (int nf = 0; nf < 8; nf++) {
            int gm = m0 + mwarp + mf * 16 + mrow;
            int gn = n0 + nwarp + nf * 8 + ncol;
            float b0 = 0.f, b1 = 0.f;
            if (bias != nullptr) { b0 = bias[gn]; b1 = bias[gn + 1]; }
            float2 lo = make_float2(F.acc[mf][nf][0] + b0, F.acc[mf][nf][1] + b1);
            float2 hi = make_float2(F.acc[mf][nf][2] + b0, F.acc[mf][nf][3] + b1);
            *reinterpret_cast<float2*>(C + (size_t)gm * N + gn)       = lo;
            *reinterpret_cast<float2*>(C + (size_t)(gm + 8) * N + gn) = hi;
        }
    }
}

// ---------------------------------------------------------------------------
// Fused QKV GEMM + per-head RMSNorm + RoPE + fp16 epilogue.
//   cols [0,2048)    -> q heads: rmsnorm+rope -> qh/ql (fp16 hi/lo)
//   cols [2048,2560) -> k heads: rmsnorm+rope -> kh (fp16 single)
//   cols [2560,3072) -> v: fp16 single -> vh
// ---------------------------------------------------------------------------
__global__ __launch_bounds__(256, 2)
void qkv_gemm_kernel(const __half* __restrict__ A2, const __half* __restrict__ B,
                     const float* __restrict__ cosp, const float* __restrict__ sinp,
                     __half* __restrict__ qh, __half* __restrict__ ql,
                     __half* __restrict__ kh, __half* __restrict__ vh)
{
    extern __shared__ __align__(1024) char smem[];
    const uint32_t su = smem_u32_of(smem);
    const int tid  = threadIdx.x;
    const int wid  = tid >> 5;
    const int lane = tid & 31;
    const int m0 = blockIdx.y * 128;
    const int n0 = blockIdx.x * 128;

    GemmFrag F;
    gemm_mainloop(A2, B, su, m0, n0, F);

    const int mwarp = (wid & 3) * 32;
    const int nwarp = (wid >> 2) * 64;
    const int mrow = lane >> 2;
    const int ncol = (lane & 3) * 2;

    if (n0 >= 2560) {
        // V region: single fp16
#pragma unroll
        for (int mf = 0; mf < 2; mf++)
#pragma unroll
            for (int nf = 0; nf < 8; nf++) {
                int gm = m0 + mwarp + mf * 16 + mrow;
                int gn = n0 - 2560 + nwarp + nf * 8 + ncol;
                store2h(vh, (size_t)gm * 512 + gn,       F.acc[mf][nf][0], F.acc[mf][nf][1]);
                store2h(vh, (size_t)(gm + 8) * 512 + gn, F.acc[mf][nf][2], F.acc[mf][nf][3]);
            }
        return;
    }

    // ---- Q/K region: RMSNorm + RoPE, all in-CTA ----
    __syncthreads();   // pipeline smem no longer needed; safe to reuse
    const int NP = 132;
    float* ntile = reinterpret_cast<float*>(smem);     // [128][132] fp32
    float* ssqp  = ntile + 128 * NP;                   // [2][128] (n-halves)
    float* rmsv  = ssqp + 256;                         // [128]

    // stage fp32 values + per-warp row ssq partials (each warp owns 64 cols)
#pragma unroll
    for (int mf = 0; mf < 2; mf++) {
        int lr0 = mwarp + mf * 16 + mrow;
        int lr1 = lr0 + 8;
        float p0 = 0.f, p1 = 0.f;
#pragma unroll
        for (int nf = 0; nf < 8; nf++) {
            int cc = nwarp + nf * 8 + ncol;
            float a0 = F.acc[mf][nf][0], a1 = F.acc[mf][nf][1];
            float a2 = F.acc[mf][nf][2], a3 = F.acc[mf][nf][3];
            ntile[lr0 * NP + cc]     = a0;
            ntile[lr0 * NP + cc + 1] = a1;
            ntile[lr1 * NP + cc]     = a2;
            ntile[lr1 * NP + cc + 1] = a3;
            p0 += a0 * a0 + a1 * a1;
            p1 += a2 * a2 + a3 * a3;
        }
        p0 += __shfl_xor_sync(0xffffffffu, p0, 1);
        p0 += __shfl_xor_sync(0xffffffffu, p0, 2);
        p1 += __shfl_xor_sync(0xffffffffu, p1, 1);
        p1 += __shfl_xor_sync(0xffffffffu, p1, 2);
        if ((lane & 3) == 0) {
            ssqp[(wid >> 2) * 128 + lr0] = p0;
            ssqp[(wid >> 2) * 128 + lr1] = p1;
        }
    }
    __syncthreads();
    if (tid < 128) {
        float s = ssqp[tid] + ssqp[128 + tid];
        rmsv[tid] = rsqrtf(s * (1.0f / 128.0f) + 1.1920929e-7f);
    }
    __syncthreads();

    // RoPE + store: 2 threads per row, 32 dims each half
    {
        int r = tid >> 1;
        int dbase = (tid & 1) * 32;
        int gm = m0 + r;
        int t  = gm & (SEQ - 1);
        float rm = rmsv[r];
        const bool isq = (n0 < 2048);
        size_t stride = isq ? 2048 : 512;
        int colbase = isq ? n0 : (n0 - 2048);
        size_t rowoff = (size_t)gm * stride + colbase;
        const float* crow = cosp + t * HALF;
        const float* srow = sinp + t * HALF;
        const float* nrow = ntile + r * NP;
#pragma unroll 4
        for (int j = 0; j < 32; j += 2) {
            int d = dbase + j;
            float v0a = nrow[d]      * rm, v1a = nrow[d + 64] * rm;
            float v0b = nrow[d + 1]  * rm, v1b = nrow[d + 65] * rm;
            float ca = crow[d],     sa = srow[d];
            float cb = crow[d + 1], sb = srow[d + 1];
            float y0 = v0a * ca - v1a * sa, y1 = v0b * cb - v1b * sb;
            float y2 = v0a * sa + v1a * ca, y3 = v0b * sb + v1b * cb;
            if (isq) {
                split_store2h(qh, ql, rowoff + d,      y0, y1);
                split_store2h(qh, ql, rowoff + 64 + d, y2, y3);
            } else {
                store2h(kh, rowoff + d,      y0, y1);
                store2h(kh, rowoff + 64 + d, y2, y3);
            }
        }
    }
}

// ---------------------------------------------------------------------------
// fp32 -> (hi, lo) fp16 split. src [M, 2048] -> dst [M, 4096] ([hi|lo]).
// ---------------------------------------------------------------------------
__global__ void split2048_kernel(const float* __restrict__ src, __half* __restrict__ dst)
{
    int i = blockIdx.x * 256 + threadIdx.x;
    float4 v = reinterpret_cast<const float4*>(src)[i];
    int e = i * 4;
    int m = e >> 11;
    int k = e & 2047;
    __half* d = dst + (size_t)m * 4096 + k;
    __half h0 = __float2half(v.x), h1 = __float2half(v.y);
    __half h2 = __float2half(v.z), h3 = __float2half(v.w);
    d[0] = h0; d[1] = h1; d[2] = h2; d[3] = h3;
    d[2048] = __float2half(v.x - __half2float(h0));
    d[2049] = __float2half(v.y - __half2float(h1));
    d[2050] = __float2half(v.z - __half2float(h2));
    d[2051] = __float2half(v.w - __half2float(h3));
}

// ---------------------------------------------------------------------------
// Transposed fp16 convert of W [2048, N] into dst columns [nbase, nbase+N),
// K-major [n][2048].
// ---------------------------------------------------------------------------
__device__ __forceinline__ void tconv_body(const float* __restrict__ W,
                                           __half* __restrict__ dst,
                                           int N, int nbase, int bx, int by)
{
    __shared__ float tl[32][33];
    int tx = threadIdx.x, ty = threadIdx.y;
    int n0 = bx * 32, k0 = by * 32;
#pragma unroll
    for (int j = 0; j < 4; j++)
        tl[ty + j * 8][tx] = W[(size_t)(k0 + ty + j * 8) * N + n0 + tx];
    __syncthreads();
#pragma unroll
    for (int j = 0; j < 4; j++) {
        int n = nbase + n0 + ty + j * 8;
        int k = k0 + tx;
        dst[(size_t)n * 2048 + k] = __float2half(tl[tx][ty + j * 8]);
    }
}

__global__ void tconv_qkv_kernel(const float* __restrict__ Wq, const float* __restrict__ Wk,
                                 const float* __restrict__ Wv, __half* __restrict__ dst)
{
    int z = blockIdx.z;
    const float* W = (z == 0) ? Wq : (z == 1) ? Wk : Wv;
    int N     = (z == 0) ? 2048 : 512;
    int nbase = (z == 0) ? 0 : (z == 1) ? 2048 : 2560;
    if ((int)blockIdx.x * 32 >= N) return;
    tconv_body(W, dst, N, nbase, blockIdx.x, blockIdx.y);
}

__global__ void tconv_wo_kernel(const float* __restrict__ W, __half* __restrict__ dst)
{
    tconv_body(W, dst, 2048, 0, blockIdx.x, blockIdx.y);
}

// ---------------------------------------------------------------------------
// fp16 HMMA flash attention, causal, GQA (unchanged from round 11).
//   S = qh*k + ql*k (2 terms).  O += ph*v + pl*v (2 terms).
// ---------------------------------------------------------------------------
#define FA_QHI 0
#define FA_QLO 32768
#define FA_K   65536
#define FA_V   98304
#define FA_PHI 131072
#define FA_PLO 147456
#define FA_SMEM 163840

__global__ __launch_bounds__(256, 1)
void flash_hmma_kernel(const __half* __restrict__ qh, const __half* __restrict__ ql,
                       const __half* __restrict__ kh, const __half* __restrict__ vh,
                       __half* __restrict__ x2)
{
    extern __shared__ __align__(1024) char smem[];
    const uint32_t su = smem_u32_of(smem);
    const int tid  = threadIdx.x;
    const int wid  = tid >> 5;
    const int lane = tid & 31;

    const int qt = (int)gridDim.x - 1 - (int)blockIdx.x;   // long CTAs first
    const int bh = blockIdx.y;
    const int b  = bh >> 4;
    const int h  = bh & 15;
    const int hkv = h >> 2;
    const int q0 = qt * 128;
    const float scale = 0.08838834764831845f;   // 1/sqrt(128)

    const __half* qhb = qh + (size_t)b * SEQ * QW + h * HDIM;
    const __half* qlb = ql + (size_t)b * SEQ * QW + h * HDIM;
    const __half* khb = kh + (size_t)b * SEQ * KW + hkv * HDIM;
    const __half* vhb = vh + (size_t)b * SEQ * KW + hkv * HDIM;

    for (int i = tid; i < 128 * 16; i += 256) {
        int r = i >> 4, c = i & 15;
        *reinterpret_cast<uint4*>(smem + FA_QHI + SW256(r, c)) =
            *reinterpret_cast<const uint4*>(qhb + (size_t)(q0 + r) * QW + c * 8);
        *reinterpret_cast<uint4*>(smem + FA_QLO + SW256(r, c)) =
            *reinterpret_cast<const uint4*>(qlb + (size_t)(q0 + r) * QW + c * 8);
    }

    const int asel = lane >> 3;
    const int arow = (lane & 7) + ((asel & 1) << 3);
    const int akc  = asel >> 1;
    const int brow = (lane & 7) + ((asel >> 1) << 3);
    const int bkc  = asel & 1;
    const int qrow_s = wid * 16 + arow;

    float o[16][4];
#pragma unroll
    for (int g = 0; g < 16; g++)
#pragma unroll
        for (int e = 0; e < 4; e++) o[g][e] = 0.f;
    float m0 = -1e30f, m1 = -1e30f, l0 = 0.f, l1 = 0.f;

    const int ntiles = 2 * qt + 2;

    auto issueKV = [&](int kt) {
        int k0 = kt * 64;
        uint32_t kb = su + FA_K + (uint32_t)(kt & 1) * 16384u;
        uint32_t vb = su + FA_V + (uint32_t)(kt & 1) * 16384u;
#pragma unroll
        for (int i = 0; i < 4; i++) {
            int id = tid + i * 256;
            int r = id >> 4, c = id & 15;
            size_t go = (size_t)(k0 + r) * KW + c * 8;
            uint32_t so = SW256(r, c);
            cp_async16(kb + so, khb + go);
            cp_async16(vb + so, vhb + go);
        }
        cp_commit();
    };

    issueKV(0);

    const int r0g = q0 + wid * 16 + (lane >> 2);
    const int r1g = r0g + 8;
    const int pr0 = wid * 16 + (lane >> 2);
    const int pr1 = pr0 + 8;

    for (int kt = 0; kt < ntiles; ++kt) {
        if (kt + 1 < ntiles) { issueKV(kt + 1); cp_wait1(); }
        else                 { cp_wait0(); }
        __syncthreads();

        uint32_t kb = su + FA_K + (uint32_t)(kt & 1) * 16384u;
        uint32_t vb = su + FA_V + (uint32_t)(kt & 1) * 16384u;

        // ---- S = QK^T (fp16, 2 terms) ----
        float s[8][4];
#pragma unroll
        for (int t = 0; t < 8; t++)
#pragma unroll
            for (int e = 0; e < 4; e++) s[t][e] = 0.f;

#pragma unroll
        for (int d = 0; d < 8; ++d) {
            uint32_t ah[4], al[4];
            ldmatrix_x4(ah, su + FA_QHI + SW256(qrow_s, d * 2 + akc));
            ldmatrix_x4(al, su + FA_QLO + SW256(qrow_s, d * 2 + akc));
#pragma unroll
            for (int j = 0; j < 4; ++j) {
                int R = j * 16 + brow;
                uint32_t kf[4];
                ldmatrix_x4(kf, kb + SW256(R, d * 2 + bkc));
                mma_fp16(s[2 * j],     ah, kf[0], kf[1]);
                mma_fp16(s[2 * j + 1], ah, kf[2], kf[3]);
                mma_fp16(s[2 * j],     al, kf[0], kf[1]);
                mma_fp16(s[2 * j + 1], al, kf[2], kf[3]);
            }
        }

        const int k0 = kt * 64;
        const bool dm = (kt >= 2 * qt);
        float mx0 = -1e30f, mx1 = -1e30f;
#pragma unroll
        for (int t = 0; t < 8; t++) {
            int c0 = k0 + t * 8 + (lane & 3) * 2;
            s[t][0] *= scale; s[t][1] *= scale; s[t][2] *= scale; s[t][3] *= scale;
            if (dm) {
                if (c0     > r0g) s[t][0] = -1e30f;
                if (c0 + 1 > r0g) s[t][1] = -1e30f;
                if (c0     > r1g) s[t][2] = -1e30f;
                if (c0 + 1 > r1g) s[t][3] = -1e30f;
            }
            mx0 = fmaxf(mx0, fmaxf(s[t][0], s[t][1]));
            mx1 = fmaxf(mx1, fmaxf(s[t][2], s[t][3]));
        }
        mx0 = fmaxf(mx0, __shfl_xor_sync(0xffffffffu, mx0, 1));
        mx0 = fmaxf(mx0, __shfl_xor_sync(0xffffffffu, mx0, 2));
        mx1 = fmaxf(mx1, __shfl_xor_sync(0xffffffffu, mx1, 1));
        mx1 = fmaxf(mx1, __shfl_xor_sync(0xffffffffu, mx1, 2));

        float mn0 = fmaxf(m0, mx0), mn1 = fmaxf(m1, mx1);
        float a0 = __expf(m0 - mn0), a1 = __expf(m1 - mn1);
        m0 = mn0; m1 = mn1;

        // ---- P = exp(S - m); split to fp16 hi/lo in smem ----
        float rs0 = 0.f, rs1 = 0.f;
#pragma unroll
        for (int t = 0; t < 8; t++) {
            float p0 = __expf(s[t][0] - m0);
            float p1 = __expf(s[t][1] - m0);
            float p2 = __expf(s[t][2] - m1);
            float p3 = __expf(s[t][3] - m1);
            rs0 += p0 + p1; rs1 += p2 + p3;
            __half h0 = __float2half(p0), h1 = __float2half(p1);
            __half h2 = __float2half(p2), h3 = __float2half(p3);
            __half2 hp01 = {h0, h1}, hp23 = {h2, h3};
            __half2 lp01 = {__float2half(p0 - __half2float(h0)),
                            __float2half(p1 - __half2float(h1))};
            __half2 lp23 = {__float2half(p2 - __half2float(h2)),
                            __float2half(p3 - __half2float(h3))};
            uint32_t o0 = (uint32_t)(pr0 * 128 + (((t) ^ (pr0 & 7)) << 4) + (lane & 3) * 4);
            uint32_t o1 = (uint32_t)(pr1 * 128 + (((t) ^ (pr1 & 7)) << 4) + (lane & 3) * 4);
            *reinterpret_cast<__half2*>(smem + FA_PHI + o0) = hp01;
            *reinterpret_cast<__half2*>(smem + FA_PHI + o1) = hp23;
            *reinterpret_cast<__half2*>(smem + FA_PLO + o0) = lp01;
            *reinterpret_cast<__half2*>(smem + FA_PLO + o1) = lp23;
        }
        rs0 += __shfl_xor_sync(0xffffffffu, rs0, 1);
        rs0 += __shfl_xor_sync(0xffffffffu, rs0, 2);
        rs1 += __shfl_xor_sync(0xffffffffu, rs1, 1);
        rs1 += __shfl_xor_sync(0xffffffffu, rs1, 2);
        l0 = l0 * a0 + rs0;
        l1 = l1 * a1 + rs1;

#pragma unroll
        for (int g = 0; g < 16; g++) {
            o[g][0] *= a0; o[g][1] *= a0; o[g][2] *= a1; o[g][3] *= a1;
        }
        __syncwarp();

        // ---- O += (ph + pl) * v ----
        const int vrow0 = (lane & 7) + ((asel & 1) << 3);
        const int vkc   = asel >> 1;
#pragma unroll
        for (int ks = 0; ks < 4; ++ks) {
            uint32_t ph[4], pl[4];
            ldmatrix_x4(ph, su + FA_PHI + SW128(qrow_s, ks * 2 + akc));
            ldmatrix_x4(pl, su + FA_PLO + SW128(qrow_s, ks * 2 + akc));
            int vr = ks * 16 + vrow0;
#pragma unroll
            for (int g = 0; g < 8; ++g) {
                uint32_t vf[4];
                ldmatrix_x4_trans(vf, vb + SW256(vr, g * 2 + vkc));
                mma_fp16(o[2 * g],     ph, vf[0], vf[1]);
                mma_fp16(o[2 * g + 1], ph, vf[2], vf[3]);
                mma_fp16(o[2 * g],     pl, vf[0], vf[1]);
                mma_fp16(o[2 * g + 1], pl, vf[2], vf[3]);
            }
        }
        __syncthreads();
    }

    float inv0 = 1.0f / l0, inv1 = 1.0f / l1;
    int row0 = b * SEQ + q0 + wid * 16 + (lane >> 2);
    int row1 = row0 + 8;
#pragma unroll
    for (int g = 0; g < 16; g++) {
        int col = h * HDIM + g * 8 + (lane & 3) * 2;
        float y0 = o[g][0] * inv0, y1 = o[g][1] * inv0;
        float y2 = o[g][2] * inv1, y3 = o[g][3] * inv1;
        split_store2h(x2, x2 + 2048, (size_t)row0 * 4096 + col, y0, y1);
        split_store2h(x2, x2 + 2048, (size_t)row1 * 4096 + col, y2, y3);
    }
}

// ---------------------------------------------------------------------------
// Launch
// ---------------------------------------------------------------------------
extern "C" void kernel_launch(void* const* d_in, const int* in_sizes, int n_in,
                              void* d_out, int out_size)
{
    const float* x    = (const float*)d_in[0];
    const float* cosp = (const float*)d_in[1];
    const float* sinp = (const float*)d_in[2];
    const float* Wq   = (const float*)d_in[3];
    const float* Wk   = (const float*)d_in[4];
    const float* Wv   = (const float*)d_in[5];
    const float* Wo   = (const float*)d_in[6];
    const float* bo   = (const float*)d_in[7];
    float* out = (float*)d_out;

    __half *x2, *wqkv, *wo2, *qh, *ql, *kh, *vh;
    cudaGetSymbolAddress((void**)&x2,   g_x2);
    cudaGetSymbolAddress((void**)&wqkv, g_wqkv);
    cudaGetSymbolAddress((void**)&wo2,  g_wo2);
    cudaGetSymbolAddress((void**)&qh,   g_qh);
    cudaGetSymbolAddress((void**)&ql,   g_ql);
    cudaGetSymbolAddress((void**)&kh,   g_kh);
    cudaGetSymbolAddress((void**)&vh,   g_vh);

    cudaFuncSetAttribute(hgemm_kernel, cudaFuncAttributeMaxDynamicSharedMemorySize, HG_SMEM);
    cudaFuncSetAttribute(qkv_gemm_kernel, cudaFuncAttributeMaxDynamicSharedMemorySize, HG_SMEM);
    cudaFuncSetAttribute(flash_hmma_kernel, cudaFuncAttributeMaxDynamicSharedMemorySize, FA_SMEM);

    // prep (order keeps qkv_gemm as our 4th launch for ncu -s 5)
    tconv_qkv_kernel<<<dim3(64, 64, 3), dim3(32, 8)>>>(Wq, Wk, Wv, wqkv);
    split2048_kernel<<<MROWS * CDIM / 4 / 256, 256>>>(x, x2);
    tconv_wo_kernel<<<dim3(64, 64), dim3(32, 8)>>>(Wo, wo2);

    // Fused QKV projection + rmsnorm + rope (fp16 2-segment GEMM, 32x64 warps)
    qkv_gemm_kernel<<<dim3(3072 / 128, MROWS / 128), 256, HG_SMEM>>>(
        x2, wqkv, cosp, sinp, qh, ql, kh, vh);

    // fp16 flash attention (writes fp16 split output into x2)
    dim3 ga(SEQ / 128, BATCH * NHEAD);
    flash_hmma_kernel<<<ga, 256, FA_SMEM>>>(qh, ql, kh, vh, x2);

    // output projection + bias (fp16 2-segment GEMM, 32x64 warps)
    hgemm_kernel<<<dim3(QW / 128, MROWS / 128), 256, HG_SMEM>>>(x2, wo2, out, QW, bo);
}

// round 15
// speedup vs baseline: 1.3807x; 1.2881x over previous
#include <cuda_runtime.h>
#include <cuda_bf16.h>
#include <cuda_fp16.h>
#include <math.h>
#include <stdint.h>

// Problem constants
#define BATCH 2
#define SEQ   2048
#define CDIM  2048
#define NHEAD 16
#define NKV   4
#define HDIM  128
#define HALF  64
#define MROWS (BATCH*SEQ)          // 4096
#define QW    (NHEAD*HDIM)         // 2048
#define KW    (NKV*HDIM)           // 512

// ---------------------------------------------------------------------------
// Scratch (device globals; no allocations allowed)
// ---------------------------------------------------------------------------
__device__ __half g_x2  [4096 * 2048];            // 16 MB fp16 (x; later attn-out)
__device__ __half g_wqkv[3072 * 2048];            // 12 MB packed [Wq|Wk|Wv]^T fp16
__device__ __half g_wo2 [2048 * 2048];            // 8 MB Wo^T fp16
__device__ __half g_qh[MROWS * QW];               // 16 MB fp16 q hi
__device__ __half g_ql[MROWS * QW];               // 16 MB fp16 q lo
__device__ __half g_kh[MROWS * KW];               // 4 MB fp16 k (single)
__device__ __half g_vh[MROWS * KW];               // 4 MB fp16 v (single)

// ---------------------------------------------------------------------------
// Baseline-PTX tensor-core helpers
// ---------------------------------------------------------------------------
__device__ __forceinline__ uint32_t smem_u32_of(const void* p) {
    uint32_t a;
    asm("{ .reg .u64 t; cvta.to.shared.u64 t, %1; cvt.u32.u64 %0, t; }" : "=r"(a) : "l"(p));
    return a;
}
__device__ __forceinline__ void cp_async16(uint32_t saddr, const void* gaddr) {
    asm volatile("cp.async.cg.shared.global [%0], [%1], 16;" :: "r"(saddr), "l"(gaddr));
}
__device__ __forceinline__ void cp_commit() {
    asm volatile("cp.async.commit_group;" ::: "memory");
}
__device__ __forceinline__ void cp_wait0() {
    asm volatile("cp.async.wait_group 0;" ::: "memory");
}
__device__ __forceinline__ void cp_wait1() {
    asm volatile("cp.async.wait_group 1;" ::: "memory");
}
__device__ __forceinline__ void ldmatrix_x4(uint32_t* r, uint32_t addr) {
    asm volatile("ldmatrix.sync.aligned.m8n8.x4.shared.b16 {%0,%1,%2,%3}, [%4];"
                 : "=r"(r[0]), "=r"(r[1]), "=r"(r[2]), "=r"(r[3]) : "r"(addr));
}
__device__ __forceinline__ void ldmatrix_x4_trans(uint32_t* r, uint32_t addr) {
    asm volatile("ldmatrix.sync.aligned.m8n8.x4.trans.shared.b16 {%0,%1,%2,%3}, [%4];"
                 : "=r"(r[0]), "=r"(r[1]), "=r"(r[2]), "=r"(r[3]) : "r"(addr));
}
__device__ __forceinline__ void mma_fp16(float* c, const uint32_t* a, uint32_t b0, uint32_t b1) {
    asm volatile(
        "mma.sync.aligned.m16n8k16.row.col.f32.f16.f16.f32 "
        "{%0,%1,%2,%3}, {%4,%5,%6,%7}, {%8,%9}, {%0,%1,%2,%3};"
        : "+f"(c[0]), "+f"(c[1]), "+f"(c[2]), "+f"(c[3])
        : "r"(a[0]), "r"(a[1]), "r"(a[2]), "r"(a[3]), "r"(b0), "r"(b1));
}

// swizzled smem offsets (16B chunks, XOR row&7)
#define SW256(r, c) ((uint32_t)((r) * 256 + (((c) ^ ((r) & 7)) << 4)))
#define SW128(r, c) ((uint32_t)((r) * 128 + (((c) ^ ((r) & 7)) << 4)))

// fp16 hi/lo split store of 2 consecutive values
__device__ __forceinline__ void split_store2h(__half* oh, __half* ol,
                                              size_t idx, float a, float b) {
    __half h0 = __float2half(a), h1 = __float2half(b);
    __half2 hp = {h0, h1};
    __half2 lp = {__float2half(a - __half2float(h0)),
                  __float2half(b - __half2float(h1))};
    *reinterpret_cast<__half2*>(oh + idx) = hp;
    *reinterpret_cast<__half2*>(ol + idx) = lp;
}
__device__ __forceinline__ void store2h(__half* o, size_t idx, float a, float b) {
    __half2 hp = {__float2half(a), __float2half(b)};
    *reinterpret_cast<__half2*>(o + idx) = hp;
}

// ===========================================================================
// fp16 GEMM core (single x single): 128x128 CTA tile, 8 warps (4x2),
// warp tile 32x64. A[M,2048] fp16 K-major, B[N,2048] fp16 K-major.
// NIT=32 k-chunks; stage = {A 16K | B 16K}. 2-stage pipeline.
// ===========================================================================
#define HG_STAGE 32768
#define HG_SMEM  (2 * HG_STAGE)
#define HG_NIT   32

struct GemmFrag { float acc[2][8][4]; };

__device__ __forceinline__ void gemm_mainloop(
    const __half* __restrict__ A, const __half* __restrict__ B,
    uint32_t su, int m0, int n0, GemmFrag& F)
{
    const int tid  = threadIdx.x;
    const int wid  = tid >> 5;
    const int lane = tid & 31;

    uint32_t smoff[4];
    const __half *gA[4], *gB[4];
#pragma unroll
    for (int i = 0; i < 4; i++) {
        int id = tid + i * 256;
        int r = id >> 3, c = id & 7;
        smoff[i] = (uint32_t)(r * 128 + ((c ^ (r & 7)) << 4));
        gA[i] = A + (size_t)(m0 + r) * 2048 + c * 8;
        gB[i] = B + (size_t)(n0 + r) * 2048 + c * 8;
    }

    const int mwarp = (wid & 3) * 32;
    const int nwarp = (wid >> 2) * 64;

    const int asel = lane >> 3;
    const int arow = (lane & 7) + ((asel & 1) << 3);
    const int akc  = asel >> 1;
    const int brow = (lane & 7) + ((asel >> 1) << 3);
    const int bkc  = asel & 1;

#pragma unroll
    for (int mf = 0; mf < 2; mf++)
#pragma unroll
        for (int nf = 0; nf < 8; nf++)
#pragma unroll
            for (int e = 0; e < 4; e++) F.acc[mf][nf][e] = 0.f;

    auto issue = [&](int t, int stage) {
        int koff = t * 64;
        uint32_t ab = su + (uint32_t)stage * (uint32_t)HG_STAGE;
        uint32_t bb = ab + 16384u;
#pragma unroll
        for (int i = 0; i < 4; i++) {
            cp_async16(ab + smoff[i], gA[i] + koff);
            cp_async16(bb + smoff[i], gB[i] + koff);
        }
        cp_commit();
    };

    issue(0, 0);
    for (int it = 0; it < HG_NIT; ++it) {
        cp_wait0();
        __syncthreads();
        if (it + 1 < HG_NIT) issue(it + 1, (it + 1) & 1);

        uint32_t ab = su + (uint32_t)(it & 1) * (uint32_t)HG_STAGE;
        uint32_t bb = ab + 16384u;

#pragma unroll
        for (int ks = 0; ks < 4; ++ks) {
            uint32_t br[4][4];
#pragma unroll
            for (int bh = 0; bh < 4; bh++) {
                int R = nwarp + bh * 16 + brow;
                int ch = ks * 2 + bkc;
                ldmatrix_x4(br[bh], bb + R * 128 + (uint32_t)((ch ^ (R & 7)) << 4));
            }
#pragma unroll
            for (int mf = 0; mf < 2; mf++) {
                int R = mwarp + mf * 16 + arow;
                uint32_t off = (uint32_t)(R * 128 + (((ks * 2 + akc) ^ (R & 7)) << 4));
                uint32_t af[4];
                ldmatrix_x4(af, ab + off);
#pragma unroll
                for (int bh = 0; bh < 4; bh++) {
                    mma_fp16(F.acc[mf][2 * bh],     af, br[bh][0], br[bh][1]);
                    mma_fp16(F.acc[mf][2 * bh + 1], af, br[bh][2], br[bh][3]);
                }
            }
        }
    }
}

// ---------------------------------------------------------------------------
// Generic GEMM with fp32 output + optional bias (used for Wo).
// ---------------------------------------------------------------------------
__global__ __launch_bounds__(256, 2)
void hgemm_kernel(const __half* __restrict__ A, const __half* __restrict__ B,
                  float* __restrict__ C, int N, const float* __restrict__ bias)
{
    extern __shared__ __align__(1024) char smem[];
    const uint32_t su = smem_u32_of(smem);
    const int tid  = threadIdx.x;
    const int wid  = tid >> 5;
    const int lane = tid & 31;
    const int m0 = blockIdx.y * 128;
    const int n0 = blockIdx.x * 128;

    GemmFrag F;
    gemm_mainloop(A, B, su, m0, n0, F);

    const int mwarp = (wid & 3) * 32;
    const int nwarp = (wid >> 2) * 64;
    const int mrow = lane >> 2;
    const int ncol = (lane & 3) * 2;
#pragma unroll
    for (int mf = 0; mf < 2; mf++) {
#pragma unroll
        for (int nf = 0; nf < 8; nf++) {
            int gm = m0 + mwarp + mf * 16 + mrow;
            int gn = n0 + nwarp + nf * 8 + ncol;
            float b0 = 0.f, b1 = 0.f;
            if (bias != nullptr) { b0 = bias[gn]; b1 = bias[gn + 1]; }
            float2 lo = make_float2(F.acc[mf][nf][0] + b0, F.acc[mf][nf][1] + b1);
            float2 hi = make_float2(F.acc[mf][nf][2] + b0, F.acc[mf][nf][3] + b1);
            *reinterpret_cast<float2*>(C + (size_t)gm * N + gn)       = lo;
            *reinterpret_cast<float2*>(C + (size_t)(gm + 8) * N + gn) = hi;
        }
    }
}

// ---------------------------------------------------------------------------
// Fused QKV GEMM + per-head RMSNorm + RoPE + fp16 epilogue.
//   cols [0,2048)    -> q heads: rmsnorm+rope -> qh/ql (fp16 hi/lo)
//   cols [2048,2560) -> k heads: rmsnorm+rope -> kh (fp16 single)
//   cols [2560,3072) -> v: fp16 single -> vh
// ---------------------------------------------------------------------------
__global__ __launch_bounds__(256, 2)
void qkv_gemm_kernel(const __half* __restrict__ A, const __half* __restrict__ B,
                     const float* __restrict__ cosp, const float* __restrict__ sinp,
                     __half* __restrict__ qh, __half* __restrict__ ql,
                     __half* __restrict__ kh, __half* __restrict__ vh)
{
    extern __shared__ __align__(1024) char smem[];
    const uint32_t su = smem_u32_of(smem);
    const int tid  = threadIdx.x;
    const int wid  = tid >> 5;
    const int lane = tid & 31;
    const int m0 = blockIdx.y * 128;
    const int n0 = blockIdx.x * 128;

    GemmFrag F;
    gemm_mainloop(A, B, su, m0, n0, F);

    const int mwarp = (wid & 3) * 32;
    const int nwarp = (wid >> 2) * 64;
    const int mrow = lane >> 2;
    const int ncol = (lane & 3) * 2;

    if (n0 >= 2560) {
        // V region: single fp16
#pragma unroll
        for (int mf = 0; mf < 2; mf++)
#pragma unroll
            for (int nf = 0; nf < 8; nf++) {
                int gm = m0 + mwarp + mf * 16 + mrow;
                int gn = n0 - 2560 + nwarp + nf * 8 + ncol;
                store2h(vh, (size_t)gm * 512 + gn,       F.acc[mf][nf][0], F.acc[mf][nf][1]);
                store2h(vh, (size_t)(gm + 8) * 512 + gn, F.acc[mf][nf][2], F.acc[mf][nf][3]);
            }
        return;
    }

    // ---- Q/K region: RMSNorm + RoPE, all in-CTA ----
    __syncthreads();   // pipeline smem no longer needed; safe to reuse
    const int NP = 132;
    float* ntile = reinterpret_cast<float*>(smem);     // [128][132] fp32 (67.5K <= 64K? no:
    // 128*132*4 = 67584 B; HG_SMEM = 65536. Use NP=126? Need 128 cols. Use NP=128 w/ offset pad:
    // Instead use NP=129 -> 128*129*4 = 66048 > 65536. So place ssqp/rmsv INSIDE padding:
    // Use NP=128 (no pad; bank conflicts acceptable in epilogue) -> 65536 exactly, and
    // put ssqp/rmsv in a small static array below.
    (void)ntile;
    float* nt = reinterpret_cast<float*>(smem);        // [128][128] fp32 = 64K
    __shared__ float ssqp[2][128];
    __shared__ float rmsv[128];

#pragma unroll
    for (int mf = 0; mf < 2; mf++) {
        int lr0 = mwarp + mf * 16 + mrow;
        int lr1 = lr0 + 8;
        float p0 = 0.f, p1 = 0.f;
#pragma unroll
        for (int nf = 0; nf < 8; nf++) {
            int cc = nwarp + nf * 8 + ncol;
            float a0 = F.acc[mf][nf][0], a1 = F.acc[mf][nf][1];
            float a2 = F.acc[mf][nf][2], a3 = F.acc[mf][nf][3];
            nt[lr0 * 128 + cc]     = a0;
            nt[lr0 * 128 + cc + 1] = a1;
            nt[lr1 * 128 + cc]     = a2;
            nt[lr1 * 128 + cc + 1] = a3;
            p0 += a0 * a0 + a1 * a1;
            p1 += a2 * a2 + a3 * a3;
        }
        p0 += __shfl_xor_sync(0xffffffffu, p0, 1);
        p0 += __shfl_xor_sync(0xffffffffu, p0, 2);
        p1 += __shfl_xor_sync(0xffffffffu, p1, 1);
        p1 += __shfl_xor_sync(0xffffffffu, p1, 2);
        if ((lane & 3) == 0) {
            ssqp[wid >> 2][lr0] = p0;
            ssqp[wid >> 2][lr1] = p1;
        }
    }
    __syncthreads();
    if (tid < 128) {
        float s = ssqp[0][tid] + ssqp[1][tid];
        rmsv[tid] = rsqrtf(s * (1.0f / 128.0f) + 1.1920929e-7f);
    }
    __syncthreads();

    // RoPE + store: 2 threads per row, 32 dims each half
    {
        int r = tid >> 1;
        int dbase = (tid & 1) * 32;
        int gm = m0 + r;
        int t  = gm & (SEQ - 1);
        float rm = rmsv[r];
        const bool isq = (n0 < 2048);
        size_t stride = isq ? 2048 : 512;
        int colbase = isq ? n0 : (n0 - 2048);
        size_t rowoff = (size_t)gm * stride + colbase;
        const float* crow = cosp + t * HALF;
        const float* srow = sinp + t * HALF;
        const float* nrow = nt + r * 128;
#pragma unroll 4
        for (int j = 0; j < 32; j += 2) {
            int d = dbase + j;
            float v0a = nrow[d]      * rm, v1a = nrow[d + 64] * rm;
            float v0b = nrow[d + 1]  * rm, v1b = nrow[d + 65] * rm;
            float ca = crow[d],     sa = srow[d];
            float cb = crow[d + 1], sb = srow[d + 1];
            float y0 = v0a * ca - v1a * sa, y1 = v0b * cb - v1b * sb;
            float y2 = v0a * sa + v1a * ca, y3 = v0b * sb + v1b * cb;
            if (isq) {
                split_store2h(qh, ql, rowoff + d,      y0, y1);
                split_store2h(qh, ql, rowoff + 64 + d, y2, y3);
            } else {
                store2h(kh, rowoff + d,      y0, y1);
                store2h(kh, rowoff + 64 + d, y2, y3);
            }
        }
    }
}

// ---------------------------------------------------------------------------
// fp32 -> fp16 convert. src [N] -> dst [N].
// ---------------------------------------------------------------------------
__global__ void conv2048_kernel(const float* __restrict__ src, __half* __restrict__ dst)
{
    int i = blockIdx.x * 256 + threadIdx.x;
    float4 v = reinterpret_cast<const float4*>(src)[i];
    __half2 a = {__float2half(v.x), __float2half(v.y)};
    __half2 b = {__float2half(v.z), __float2half(v.w)};
    reinterpret_cast<__half2*>(dst)[i * 2]     = a;
    reinterpret_cast<__half2*>(dst)[i * 2 + 1] = b;
}

// ---------------------------------------------------------------------------
// Transposed fp16 convert of W [2048, N] into dst columns [nbase, nbase+N),
// K-major [n][2048].
// ---------------------------------------------------------------------------
__device__ __forceinline__ void tconv_body(const float* __restrict__ W,
                                           __half* __restrict__ dst,
                                           int N, int nbase, int bx, int by)
{
    __shared__ float tl[32][33];
    int tx = threadIdx.x, ty = threadIdx.y;
    int n0 = bx * 32, k0 = by * 32;
#pragma unroll
    for (int j = 0; j < 4; j++)
        tl[ty + j * 8][tx] = W[(size_t)(k0 + ty + j * 8) * N + n0 + tx];
    __syncthreads();
#pragma unroll
    for (int j = 0; j < 4; j++) {
        int n = nbase + n0 + ty + j * 8;
        int k = k0 + tx;
        dst[(size_t)n * 2048 + k] = __float2half(tl[tx][ty + j * 8]);
    }
}

__global__ void tconv_qkv_kernel(const float* __restrict__ Wq, const float* __restrict__ Wk,
                                 const float* __restrict__ Wv, __half* __restrict__ dst)
{
    int z = blockIdx.z;
    const float* W = (z == 0) ? Wq : (z == 1) ? Wk : Wv;
    int N     = (z == 0) ? 2048 : 512;
    int nbase = (z == 0) ? 0 : (z == 1) ? 2048 : 2560;
    if ((int)blockIdx.x * 32 >= N) return;
    tconv_body(W, dst, N, nbase, blockIdx.x, blockIdx.y);
}

__global__ void tconv_wo_kernel(const float* __restrict__ W, __half* __restrict__ dst)
{
    tconv_body(W, dst, 2048, 0, blockIdx.x, blockIdx.y);
}

// ---------------------------------------------------------------------------
// fp16 HMMA flash attention, causal, GQA.
//   S = qh*k + ql*k (2 terms).  O += ph*v + pl*v (2 terms).
// Output: single fp16 into x2 [row][0..2047].
// ---------------------------------------------------------------------------
#define FA_QHI 0
#define FA_QLO 32768
#define FA_K   65536
#define FA_V   98304
#define FA_PHI 131072
#define FA_PLO 147456
#define FA_SMEM 163840

__global__ __launch_bounds__(256, 1)
void flash_hmma_kernel(const __half* __restrict__ qh, const __half* __restrict__ ql,
                       const __half* __restrict__ kh, const __half* __restrict__ vh,
                       __half* __restrict__ x2)
{
    extern __shared__ __align__(1024) char smem[];
    const uint32_t su = smem_u32_of(smem);
    const int tid  = threadIdx.x;
    const int wid  = tid >> 5;
    const int lane = tid & 31;

    const int qt = (int)gridDim.x - 1 - (int)blockIdx.x;   // long CTAs first
    const int bh = blockIdx.y;
    const int b  = bh >> 4;
    const int h  = bh & 15;
    const int hkv = h >> 2;
    const int q0 = qt * 128;
    const float scale = 0.08838834764831845f;   // 1/sqrt(128)

    const __half* qhb = qh + (size_t)b * SEQ * QW + h * HDIM;
    const __half* qlb = ql + (size_t)b * SEQ * QW + h * HDIM;
    const __half* khb = kh + (size_t)b * SEQ * KW + hkv * HDIM;
    const __half* vhb = vh + (size_t)b * SEQ * KW + hkv * HDIM;

    for (int i = tid; i < 128 * 16; i += 256) {
        int r = i >> 4, c = i & 15;
        *reinterpret_cast<uint4*>(smem + FA_QHI + SW256(r, c)) =
            *reinterpret_cast<const uint4*>(qhb + (size_t)(q0 + r) * QW + c * 8);
        *reinterpret_cast<uint4*>(smem + FA_QLO + SW256(r, c)) =
            *reinterpret_cast<const uint4*>(qlb + (size_t)(q0 + r) * QW + c * 8);
    }

    const int asel = lane >> 3;
    const int arow = (lane & 7) + ((asel & 1) << 3);
    const int akc  = asel >> 1;
    const int brow = (lane & 7) + ((asel >> 1) << 3);
    const int bkc  = asel & 1;
    const int qrow_s = wid * 16 + arow;

    float o[16][4];
#pragma unroll
    for (int g = 0; g < 16; g++)
#pragma unroll
        for (int e = 0; e < 4; e++) o[g][e] = 0.f;
    float m0 = -1e30f, m1 = -1e30f, l0 = 0.f, l1 = 0.f;

    const int ntiles = 2 * qt + 2;

    auto issueKV = [&](int kt) {
        int k0 = kt * 64;
        uint32_t kb = su + FA_K + (uint32_t)(kt & 1) * 16384u;
        uint32_t vb = su + FA_V + (uint32_t)(kt & 1) * 16384u;
#pragma unroll
        for (int i = 0; i < 4; i++) {
            int id = tid + i * 256;
            int r = id >> 4, c = id & 15;
            size_t go = (size_t)(k0 + r) * KW + c * 8;
            uint32_t so = SW256(r, c);
            cp_async16(kb + so, khb + go);
            cp_async16(vb + so, vhb + go);
        }
        cp_commit();
    };

    issueKV(0);

    const int r0g = q0 + wid * 16 + (lane >> 2);
    const int r1g = r0g + 8;
    const int pr0 = wid * 16 + (lane >> 2);
    const int pr1 = pr0 + 8;

    for (int kt = 0; kt < ntiles; ++kt) {
        if (kt + 1 < ntiles) { issueKV(kt + 1); cp_wait1(); }
        else                 { cp_wait0(); }
        __syncthreads();

        uint32_t kb = su + FA_K + (uint32_t)(kt & 1) * 16384u;
        uint32_t vb = su + FA_V + (uint32_t)(kt & 1) * 16384u;

        // ---- S = QK^T (fp16, 2 terms) ----
        float s[8][4];
#pragma unroll
        for (int t = 0; t < 8; t++)
#pragma unroll
            for (int e = 0; e < 4; e++) s[t][e] = 0.f;

#pragma unroll
        for (int d = 0; d < 8; ++d) {
            uint32_t ah[4], al[4];
            ldmatrix_x4(ah, su + FA_QHI + SW256(qrow_s, d * 2 + akc));
            ldmatrix_x4(al, su + FA_QLO + SW256(qrow_s, d * 2 + akc));
#pragma unroll
            for (int j = 0; j < 4; ++j) {
                int R = j * 16 + brow;
                uint32_t kf[4];
                ldmatrix_x4(kf, kb + SW256(R, d * 2 + bkc));
                mma_fp16(s[2 * j],     ah, kf[0], kf[1]);
                mma_fp16(s[2 * j + 1], ah, kf[2], kf[3]);
                mma_fp16(s[2 * j],     al, kf[0], kf[1]);
                mma_fp16(s[2 * j + 1], al, kf[2], kf[3]);
            }
        }

        const int k0 = kt * 64;
        const bool dm = (kt >= 2 * qt);
        float mx0 = -1e30f, mx1 = -1e30f;
#pragma unroll
        for (int t = 0; t < 8; t++) {
            int c0 = k0 + t * 8 + (lane & 3) * 2;
            s[t][0] *= scale; s[t][1] *= scale; s[t][2] *= scale; s[t][3] *= scale;
            if (dm) {
                if (c0     > r0g) s[t][0] = -1e30f;
                if (c0 + 1 > r0g) s[t][1] = -1e30f;
                if (c0     > r1g) s[t][2] = -1e30f;
                if (c0 + 1 > r1g) s[t][3] = -1e30f;
            }
            mx0 = fmaxf(mx0, fmaxf(s[t][0], s[t][1]));
            mx1 = fmaxf(mx1, fmaxf(s[t][2], s[t][3]));
        }
        mx0 = fmaxf(mx0, __shfl_xor_sync(0xffffffffu, mx0, 1));
        mx0 = fmaxf(mx0, __shfl_xor_sync(0xffffffffu, mx0, 2));
        mx1 = fmaxf(mx1, __shfl_xor_sync(0xffffffffu, mx1, 1));
        mx1 = fmaxf(mx1, __shfl_xor_sync(0xffffffffu, mx1, 2));

        float mn0 = fmaxf(m0, mx0), mn1 = fmaxf(m1, mx1);
        float a0 = __expf(m0 - mn0), a1 = __expf(m1 - mn1);
        m0 = mn0; m1 = mn1;

        // ---- P = exp(S - m); split to fp16 hi/lo in smem ----
        float rs0 = 0.f, rs1 = 0.f;
#pragma unroll
        for (int t = 0; t < 8; t++) {
            float p0 = __expf(s[t][0] - m0);
            float p1 = __expf(s[t][1] - m0);
            float p2 = __expf(s[t][2] - m1);
            float p3 = __expf(s[t][3] - m1);
            rs0 += p0 + p1; rs1 += p2 + p3;
            __half h0 = __float2half(p0), h1 = __float2half(p1);
            __half h2 = __float2half(p2), h3 = __float2half(p3);
            __half2 hp01 = {h0, h1}, hp23 = {h2, h3};
            __half2 lp01 = {__float2half(p0 - __half2float(h0)),
                            __float2half(p1 - __half2float(h1))};
            __half2 lp23 = {__float2half(p2 - __half2float(h2)),
                            __float2half(p3 - __half2float(h3))};
            uint32_t o0 = (uint32_t)(pr0 * 128 + (((t) ^ (pr0 & 7)) << 4) + (lane & 3) * 4);
            uint32_t o1 = (uint32_t)(pr1 * 128 + (((t) ^ (pr1 & 7)) << 4) + (lane & 3) * 4);
            *reinterpret_cast<__half2*>(smem + FA_PHI + o0) = hp01;
            *reinterpret_cast<__half2*>(smem + FA_PHI + o1) = hp23;
            *reinterpret_cast<__half2*>(smem + FA_PLO + o0) = lp01;
            *reinterpret_cast<__half2*>(smem + FA_PLO + o1) = lp23;
        }
        rs0 += __shfl_xor_sync(0xffffffffu, rs0, 1);
        rs0 += __shfl_xor_sync(0xffffffffu, rs0, 2);
        rs1 += __shfl_xor_sync(0xffffffffu, rs1, 1);
        rs1 += __shfl_xor_sync(0xffffffffu, rs1, 2);
        l0 = l0 * a0 + rs0;
        l1 = l1 * a1 + rs1;

#pragma unroll
        for (int g = 0; g < 16; g++) {
            o[g][0] *= a0; o[g][1] *= a0; o[g][2] *= a1; o[g][3] *= a1;
        }
        __syncwarp();

        // ---- O += (ph + pl) * v ----
        const int vrow0 = (lane & 7) + ((asel & 1) << 3);
        const int vkc   = asel >> 1;
#pragma unroll
        for (int ks = 0; ks < 4; ++ks) {
            uint32_t ph[4], pl[4];
            ldmatrix_x4(ph, su + FA_PHI + SW128(qrow_s, ks * 2 + akc));
            ldmatrix_x4(pl, su + FA_PLO + SW128(qrow_s, ks * 2 + akc));
            int vr = ks * 16 + vrow0;
#pragma unroll
            for (int g = 0; g < 8; ++g) {
                uint32_t vf[4];
                ldmatrix_x4_trans(vf, vb + SW256(vr, g * 2 + vkc));
                mma_fp16(o[2 * g],     ph, vf[0], vf[1]);
                mma_fp16(o[2 * g + 1], ph, vf[2], vf[3]);
                mma_fp16(o[2 * g],     pl, vf[0], vf[1]);
                mma_fp16(o[2 * g + 1], pl, vf[2], vf[3]);
            }
        }
        __syncthreads();
    }

    float inv0 = 1.0f / l0, inv1 = 1.0f / l1;
    int row0 = b * SEQ + q0 + wid * 16 + (lane >> 2);
    int row1 = row0 + 8;
#pragma unroll
    for (int g = 0; g < 16; g++) {
        int col = h * HDIM + g * 8 + (lane & 3) * 2;
        float y0 = o[g][0] * inv0, y1 = o[g][1] * inv0;
        float y2 = o[g][2] * inv1, y3 = o[g][3] * inv1;
        store2h(x2, (size_t)row0 * 2048 + col, y0, y1);
        store2h(x2, (size_t)row1 * 2048 + col, y2, y3);
    }
}

// ---------------------------------------------------------------------------
// Launch
// ---------------------------------------------------------------------------
extern "C" void kernel_launch(void* const* d_in, const int* in_sizes, int n_in,
                              void* d_out, int out_size)
{
    const float* x    = (const float*)d_in[0];
    const float* cosp = (const float*)d_in[1];
    const float* sinp = (const float*)d_in[2];
    const float* Wq   = (const float*)d_in[3];
    const float* Wk   = (const float*)d_in[4];
    const float* Wv   = (const float*)d_in[5];
    const float* Wo   = (const float*)d_in[6];
    const float* bo   = (const float*)d_in[7];
    float* out = (float*)d_out;

    __half *x2, *wqkv, *wo2, *qh, *ql, *kh, *vh;
    cudaGetSymbolAddress((void**)&x2,   g_x2);
    cudaGetSymbolAddress((void**)&wqkv, g_wqkv);
    cudaGetSymbolAddress((void**)&wo2,  g_wo2);
    cudaGetSymbolAddress((void**)&qh,   g_qh);
    cudaGetSymbolAddress((void**)&ql,   g_ql);
    cudaGetSymbolAddress((void**)&kh,   g_kh);
    cudaGetSymbolAddress((void**)&vh,   g_vh);

    cudaFuncSetAttribute(hgemm_kernel, cudaFuncAttributeMaxDynamicSharedMemorySize, HG_SMEM);
    cudaFuncSetAttribute(qkv_gemm_kernel, cudaFuncAttributeMaxDynamicSharedMemorySize, HG_SMEM);
    cudaFuncSetAttribute(flash_hmma_kernel, cudaFuncAttributeMaxDynamicSharedMemorySize, FA_SMEM);

    // prep (order keeps qkv_gemm as our 4th launch for ncu -s 5)
    tconv_qkv_kernel<<<dim3(64, 64, 3), dim3(32, 8)>>>(Wq, Wk, Wv, wqkv);
    conv2048_kernel<<<MROWS * CDIM / 4 / 256, 256>>>(x, x2);
    tconv_wo_kernel<<<dim3(64, 64), dim3(32, 8)>>>(Wo, wo2);

    // Fused QKV projection + rmsnorm + rope (fp16 single x single GEMM)
    qkv_gemm_kernel<<<dim3(3072 / 128, MROWS / 128), 256, HG_SMEM>>>(
        x2, wqkv, cosp, sinp, qh, ql, kh, vh);

    // fp16 flash attention (writes single fp16 output into x2)
    dim3 ga(SEQ / 128, BATCH * NHEAD);
    flash_hmma_kernel<<<ga, 256, FA_SMEM>>>(qh, ql, kh, vh, x2);

    // output projection + bias (fp16 single x single GEMM)
    hgemm_kernel<<<dim3(QW / 128, MROWS / 128), 256, HG_SMEM>>>(x2, wo2, out, QW, bo);
}

// round 16
// speedup vs baseline: 1.4381x; 1.0415x over previous
#include <cuda_runtime.h>
#include <cuda_bf16.h>
#include <cuda_fp16.h>
#include <math.h>
#include <stdint.h>

// Problem constants
#define BATCH 2
#define SEQ   2048
#define CDIM  2048
#define NHEAD 16
#define NKV   4
#define HDIM  128
#define HALF  64
#define MROWS (BATCH*SEQ)          // 4096
#define QW    (NHEAD*HDIM)         // 2048
#define KW    (NKV*HDIM)           // 512

// ---------------------------------------------------------------------------
// Scratch (device globals; no allocations allowed)
// ---------------------------------------------------------------------------
__device__ __half g_x2  [4096 * 2048];            // 16 MB fp16 (x; later attn-out)
__device__ __half g_wqkv[3072 * 2048];            // 12 MB packed [Wq|Wk|Wv]^T fp16
__device__ __half g_wo2 [2048 * 2048];            // 8 MB Wo^T fp16
__device__ __half g_qh[MROWS * QW];               // 16 MB fp16 q hi
__device__ __half g_ql[MROWS * QW];               // 16 MB fp16 q lo
__device__ __half g_kh[MROWS * KW];               // 4 MB fp16 k (single)
__device__ __half g_vh[MROWS * KW];               // 4 MB fp16 v (single)

// ---------------------------------------------------------------------------
// Baseline-PTX tensor-core helpers
// ---------------------------------------------------------------------------
__device__ __forceinline__ uint32_t smem_u32_of(const void* p) {
    uint32_t a;
    asm("{ .reg .u64 t; cvta.to.shared.u64 t, %1; cvt.u32.u64 %0, t; }" : "=r"(a) : "l"(p));
    return a;
}
__device__ __forceinline__ void cp_async16(uint32_t saddr, const void* gaddr) {
    asm volatile("cp.async.cg.shared.global [%0], [%1], 16;" :: "r"(saddr), "l"(gaddr));
}
__device__ __forceinline__ void cp_commit() {
    asm volatile("cp.async.commit_group;" ::: "memory");
}
__device__ __forceinline__ void cp_wait0() {
    asm volatile("cp.async.wait_group 0;" ::: "memory");
}
__device__ __forceinline__ void cp_wait1() {
    asm volatile("cp.async.wait_group 1;" ::: "memory");
}
__device__ __forceinline__ void ldmatrix_x4(uint32_t* r, uint32_t addr) {
    asm volatile("ldmatrix.sync.aligned.m8n8.x4.shared.b16 {%0,%1,%2,%3}, [%4];"
                 : "=r"(r[0]), "=r"(r[1]), "=r"(r[2]), "=r"(r[3]) : "r"(addr));
}
__device__ __forceinline__ void ldmatrix_x4_trans(uint32_t* r, uint32_t addr) {
    asm volatile("ldmatrix.sync.aligned.m8n8.x4.trans.shared.b16 {%0,%1,%2,%3}, [%4];"
                 : "=r"(r[0]), "=r"(r[1]), "=r"(r[2]), "=r"(r[3]) : "r"(addr));
}
__device__ __forceinline__ void mma_fp16(float* c, const uint32_t* a, uint32_t b0, uint32_t b1) {
    asm volatile(
        "mma.sync.aligned.m16n8k16.row.col.f32.f16.f16.f32 "
        "{%0,%1,%2,%3}, {%4,%5,%6,%7}, {%8,%9}, {%0,%1,%2,%3};"
        : "+f"(c[0]), "+f"(c[1]), "+f"(c[2]), "+f"(c[3])
        : "r"(a[0]), "r"(a[1]), "r"(a[2]), "r"(a[3]), "r"(b0), "r"(b1));
}

// swizzled smem offsets (16B chunks, XOR row&7)
#define SW256(r, c) ((uint32_t)((r) * 256 + (((c) ^ ((r) & 7)) << 4)))

// fp16 hi/lo split store of 2 consecutive values
__device__ __forceinline__ void split_store2h(__half* oh, __half* ol,
                                              size_t idx, float a, float b) {
    __half h0 = __float2half(a), h1 = __float2half(b);
    __half2 hp = {h0, h1};
    __half2 lp = {__float2half(a - __half2float(h0)),
                  __float2half(b - __half2float(h1))};
    *reinterpret_cast<__half2*>(oh + idx) = hp;
    *reinterpret_cast<__half2*>(ol + idx) = lp;
}
__device__ __forceinline__ void store2h(__half* o, size_t idx, float a, float b) {
    __half2 hp = {__float2half(a), __float2half(b)};
    *reinterpret_cast<__half2*>(o + idx) = hp;
}
// pack two floats into fp16x2 hi + residual lo (register-resident P split)
__device__ __forceinline__ void split_pack2(float a, float b, uint32_t& hi, uint32_t& lo) {
    __half ha = __float2half(a), hb = __float2half(b);
    __half2 h = {ha, hb};
    hi = *reinterpret_cast<uint32_t*>(&h);
    __half2 l = {__float2half(a - __half2float(ha)),
                 __float2half(b - __half2float(hb))};
    lo = *reinterpret_cast<uint32_t*>(&l);
}

// ===========================================================================
// fp16 GEMM core (single x single): 128x128 CTA tile, 8 warps (4x2),
// warp tile 32x64. A[M,2048] fp16 K-major, B[N,2048] fp16 K-major.
// NIT=32 k-chunks; stage = {A 16K | B 16K}. 2-stage pipeline.
// ===========================================================================
#define HG_STAGE 32768
#define HG_SMEM  (2 * HG_STAGE)
#define HG_NIT   32

struct GemmFrag { float acc[2][8][4]; };

__device__ __forceinline__ void gemm_mainloop(
    const __half* __restrict__ A, const __half* __restrict__ B,
    uint32_t su, int m0, int n0, GemmFrag& F)
{
    const int tid  = threadIdx.x;
    const int wid  = tid >> 5;
    const int lane = tid & 31;

    uint32_t smoff[4];
    const __half *gA[4], *gB[4];
#pragma unroll
    for (int i = 0; i < 4; i++) {
        int id = tid + i * 256;
        int r = id >> 3, c = id & 7;
        smoff[i] = (uint32_t)(r * 128 + ((c ^ (r & 7)) << 4));
        gA[i] = A + (size_t)(m0 + r) * 2048 + c * 8;
        gB[i] = B + (size_t)(n0 + r) * 2048 + c * 8;
    }

    const int mwarp = (wid & 3) * 32;
    const int nwarp = (wid >> 2) * 64;

    const int asel = lane >> 3;
    const int arow = (lane & 7) + ((asel & 1) << 3);
    const int akc  = asel >> 1;
    const int brow = (lane & 7) + ((asel >> 1) << 3);
    const int bkc  = asel & 1;

#pragma unroll
    for (int mf = 0; mf < 2; mf++)
#pragma unroll
        for (int nf = 0; nf < 8; nf++)
#pragma unroll
            for (int e = 0; e < 4; e++) F.acc[mf][nf][e] = 0.f;

    auto issue = [&](int t, int stage) {
        int koff = t * 64;
        uint32_t ab = su + (uint32_t)stage * (uint32_t)HG_STAGE;
        uint32_t bb = ab + 16384u;
#pragma unroll
        for (int i = 0; i < 4; i++) {
            cp_async16(ab + smoff[i], gA[i] + koff);
            cp_async16(bb + smoff[i], gB[i] + koff);
        }
        cp_commit();
    };

    issue(0, 0);
    for (int it = 0; it < HG_NIT; ++it) {
        cp_wait0();
        __syncthreads();
        if (it + 1 < HG_NIT) issue(it + 1, (it + 1) & 1);

        uint32_t ab = su + (uint32_t)(it & 1) * (uint32_t)HG_STAGE;
        uint32_t bb = ab + 16384u;

#pragma unroll
        for (int ks = 0; ks < 4; ++ks) {
            uint32_t br[4][4];
#pragma unroll
            for (int bh = 0; bh < 4; bh++) {
                int R = nwarp + bh * 16 + brow;
                int ch = ks * 2 + bkc;
                ldmatrix_x4(br[bh], bb + R * 128 + (uint32_t)((ch ^ (R & 7)) << 4));
            }
#pragma unroll
            for (int mf = 0; mf < 2; mf++) {
                int R = mwarp + mf * 16 + arow;
                uint32_t off = (uint32_t)(R * 128 + (((ks * 2 + akc) ^ (R & 7)) << 4));
                uint32_t af[4];
                ldmatrix_x4(af, ab + off);
#pragma unroll
                for (int bh = 0; bh < 4; bh++) {
                    mma_fp16(F.acc[mf][2 * bh],     af, br[bh][0], br[bh][1]);
                    mma_fp16(F.acc[mf][2 * bh + 1], af, br[bh][2], br[bh][3]);
                }
            }
        }
    }
}

// ---------------------------------------------------------------------------
// Generic GEMM with fp32 output + optional bias (used for Wo).
// ---------------------------------------------------------------------------
__global__ __launch_bounds__(256, 2)
void hgemm_kernel(const __half* __restrict__ A, const __half* __restrict__ B,
                  float* __restrict__ C, int N, const float* __restrict__ bias)
{
    extern __shared__ __align__(1024) char smem[];
    const uint32_t su = smem_u32_of(smem);
    const int tid  = threadIdx.x;
    const int wid  = tid >> 5;
    const int lane = tid & 31;
    const int m0 = blockIdx.y * 128;
    const int n0 = blockIdx.x * 128;

    GemmFrag F;
    gemm_mainloop(A, B, su, m0, n0, F);

    const int mwarp = (wid & 3) * 32;
    const int nwarp = (wid >> 2) * 64;
    const int mrow = lane >> 2;
    const int ncol = (lane & 3) * 2;
#pragma unroll
    for (int mf = 0; mf < 2; mf++) {
#pragma unroll
        for (int nf = 0; nf < 8; nf++) {
            int gm = m0 + mwarp + mf * 16 + mrow;
            int gn = n0 + nwarp + nf * 8 + ncol;
            float b0 = 0.f, b1 = 0.f;
            if (bias != nullptr) { b0 = bias[gn]; b1 = bias[gn + 1]; }
            float2 lo = make_float2(F.acc[mf][nf][0] + b0, F.acc[mf][nf][1] + b1);
            float2 hi = make_float2(F.acc[mf][nf][2] + b0, F.acc[mf][nf][3] + b1);
            *reinterpret_cast<float2*>(C + (size_t)gm * N + gn)       = lo;
            *reinterpret_cast<float2*>(C + (size_t)(gm + 8) * N + gn) = hi;
        }
    }
}

// ---------------------------------------------------------------------------
// Fused QKV GEMM + per-head RMSNorm + RoPE + fp16 epilogue.
//   cols [0,2048)    -> q heads: rmsnorm+rope -> qh/ql (fp16 hi/lo)
//   cols [2048,2560) -> k heads: rmsnorm+rope -> kh (fp16 single)
//   cols [2560,3072) -> v: fp16 single -> vh
// ---------------------------------------------------------------------------
__global__ __launch_bounds__(256, 2)
void qkv_gemm_kernel(const __half* __restrict__ A, const __half* __restrict__ B,
                     const float* __restrict__ cosp, const float* __restrict__ sinp,
                     __half* __restrict__ qh, __half* __restrict__ ql,
                     __half* __restrict__ kh, __half* __restrict__ vh)
{
    extern __shared__ __align__(1024) char smem[];
    const uint32_t su = smem_u32_of(smem);
    const int tid  = threadIdx.x;
    const int wid  = tid >> 5;
    const int lane = tid & 31;
    const int m0 = blockIdx.y * 128;
    const int n0 = blockIdx.x * 128;

    GemmFrag F;
    gemm_mainloop(A, B, su, m0, n0, F);

    const int mwarp = (wid & 3) * 32;
    const int nwarp = (wid >> 2) * 64;
    const int mrow = lane >> 2;
    const int ncol = (lane & 3) * 2;

    if (n0 >= 2560) {
        // V region: single fp16
#pragma unroll
        for (int mf = 0; mf < 2; mf++)
#pragma unroll
            for (int nf = 0; nf < 8; nf++) {
                int gm = m0 + mwarp + mf * 16 + mrow;
                int gn = n0 - 2560 + nwarp + nf * 8 + ncol;
                store2h(vh, (size_t)gm * 512 + gn,       F.acc[mf][nf][0], F.acc[mf][nf][1]);
                store2h(vh, (size_t)(gm + 8) * 512 + gn, F.acc[mf][nf][2], F.acc[mf][nf][3]);
            }
        return;
    }

    // ---- Q/K region: RMSNorm + RoPE, all in-CTA ----
    __syncthreads();   // pipeline smem no longer needed; safe to reuse
    float* nt = reinterpret_cast<float*>(smem);        // [128][128] fp32 = 64K
    __shared__ float ssqp[2][128];
    __shared__ float rmsv[128];

#pragma unroll
    for (int mf = 0; mf < 2; mf++) {
        int lr0 = mwarp + mf * 16 + mrow;
        int lr1 = lr0 + 8;
        float p0 = 0.f, p1 = 0.f;
#pragma unroll
        for (int nf = 0; nf < 8; nf++) {
            int cc = nwarp + nf * 8 + ncol;
            float a0 = F.acc[mf][nf][0], a1 = F.acc[mf][nf][1];
            float a2 = F.acc[mf][nf][2], a3 = F.acc[mf][nf][3];
            nt[lr0 * 128 + cc]     = a0;
            nt[lr0 * 128 + cc + 1] = a1;
            nt[lr1 * 128 + cc]     = a2;
            nt[lr1 * 128 + cc + 1] = a3;
            p0 += a0 * a0 + a1 * a1;
            p1 += a2 * a2 + a3 * a3;
        }
        p0 += __shfl_xor_sync(0xffffffffu, p0, 1);
        p0 += __shfl_xor_sync(0xffffffffu, p0, 2);
        p1 += __shfl_xor_sync(0xffffffffu, p1, 1);
        p1 += __shfl_xor_sync(0xffffffffu, p1, 2);
        if ((lane & 3) == 0) {
            ssqp[wid >> 2][lr0] = p0;
            ssqp[wid >> 2][lr1] = p1;
        }
    }
    __syncthreads();
    if (tid < 128) {
        float s = ssqp[0][tid] + ssqp[1][tid];
        rmsv[tid] = rsqrtf(s * (1.0f / 128.0f) + 1.1920929e-7f);
    }
    __syncthreads();

    // RoPE + store: 2 threads per row, 32 dims each half
    {
        int r = tid >> 1;
        int dbase = (tid & 1) * 32;
        int gm = m0 + r;
        int t  = gm & (SEQ - 1);
        float rm = rmsv[r];
        const bool isq = (n0 < 2048);
        size_t stride = isq ? 2048 : 512;
        int colbase = isq ? n0 : (n0 - 2048);
        size_t rowoff = (size_t)gm * stride + colbase;
        const float* crow = cosp + t * HALF;
        const float* srow = sinp + t * HALF;
        const float* nrow = nt + r * 128;
#pragma unroll 4
        for (int j = 0; j < 32; j += 2) {
            int d = dbase + j;
            float v0a = nrow[d]      * rm, v1a = nrow[d + 64] * rm;
            float v0b = nrow[d + 1]  * rm, v1b = nrow[d + 65] * rm;
            float ca = crow[d],     sa = srow[d];
            float cb = crow[d + 1], sb = srow[d + 1];
            float y0 = v0a * ca - v1a * sa, y1 = v0b * cb - v1b * sb;
            float y2 = v0a * sa + v1a * ca, y3 = v0b * sb + v1b * cb;
            if (isq) {
                split_store2h(qh, ql, rowoff + d,      y0, y1);
                split_store2h(qh, ql, rowoff + 64 + d, y2, y3);
            } else {
                store2h(kh, rowoff + d,      y0, y1);
                store2h(kh, rowoff + 64 + d, y2, y3);
            }
        }
    }
}

// ---------------------------------------------------------------------------
// fp32 -> fp16 convert.
// ---------------------------------------------------------------------------
__global__ void conv2048_kernel(const float* __restrict__ src, __half* __restrict__ dst)
{
    int i = blockIdx.x * 256 + threadIdx.x;
    float4 v = reinterpret_cast<const float4*>(src)[i];
    __half2 a = {__float2half(v.x), __float2half(v.y)};
    __half2 b = {__float2half(v.z), __float2half(v.w)};
    reinterpret_cast<__half2*>(dst)[i * 2]     = a;
    reinterpret_cast<__half2*>(dst)[i * 2 + 1] = b;
}

// ---------------------------------------------------------------------------
// Transposed fp16 convert of W [2048, N] into dst columns [nbase, nbase+N),
// K-major [n][2048].
// ---------------------------------------------------------------------------
__device__ __forceinline__ void tconv_body(const float* __restrict__ W,
                                           __half* __restrict__ dst,
                                           int N, int nbase, int bx, int by)
{
    __shared__ float tl[32][33];
    int tx = threadIdx.x, ty = threadIdx.y;
    int n0 = bx * 32, k0 = by * 32;
#pragma unroll
    for (int j = 0; j < 4; j++)
        tl[ty + j * 8][tx] = W[(size_t)(k0 + ty + j * 8) * N + n0 + tx];
    __syncthreads();
#pragma unroll
    for (int j = 0; j < 4; j++) {
        int n = nbase + n0 + ty + j * 8;
        int k = k0 + tx;
        dst[(size_t)n * 2048 + k] = __float2half(tl[tx][ty + j * 8]);
    }
}

__global__ void tconv_qkv_kernel(const float* __restrict__ Wq, const float* __restrict__ Wk,
                                 const float* __restrict__ Wv, __half* __restrict__ dst)
{
    int z = blockIdx.z;
    const float* W = (z == 0) ? Wq : (z == 1) ? Wk : Wv;
    int N     = (z == 0) ? 2048 : 512;
    int nbase = (z == 0) ? 0 : (z == 1) ? 2048 : 2560;
    if ((int)blockIdx.x * 32 >= N) return;
    tconv_body(W, dst, N, nbase, blockIdx.x, blockIdx.y);
}

__global__ void tconv_wo_kernel(const float* __restrict__ W, __half* __restrict__ dst)
{
    tconv_body(W, dst, 2048, 0, blockIdx.x, blockIdx.y);
}

// ---------------------------------------------------------------------------
// fp16 HMMA flash attention, causal, GQA.
//   S = qh*k + ql*k (2 terms).  O += ph*v + pl*v (2 terms, P split in REGISTERS
//   — accumulator fragment doubles as A-operand fragment, no smem round trip).
// Smem: Qhi 32K | Qlo 32K | K 2st 32K | V 2st 32K = 128K
// ---------------------------------------------------------------------------
#define FA_QHI 0
#define FA_QLO 32768
#define FA_K   65536
#define FA_V   98304
#define FA_SMEM 131072

__global__ __launch_bounds__(256, 1)
void flash_hmma_kernel(const __half* __restrict__ qh, const __half* __restrict__ ql,
                       const __half* __restrict__ kh, const __half* __restrict__ vh,
                       __half* __restrict__ x2)
{
    extern __shared__ __align__(1024) char smem[];
    const uint32_t su = smem_u32_of(smem);
    const int tid  = threadIdx.x;
    const int wid  = tid >> 5;
    const int lane = tid & 31;

    const int qt = (int)gridDim.x - 1 - (int)blockIdx.x;   // long CTAs first
    const int bh = blockIdx.y;
    const int b  = bh >> 4;
    const int h  = bh & 15;
    const int hkv = h >> 2;
    const int q0 = qt * 128;
    const float scale = 0.08838834764831845f;   // 1/sqrt(128)

    const __half* qhb = qh + (size_t)b * SEQ * QW + h * HDIM;
    const __half* qlb = ql + (size_t)b * SEQ * QW + h * HDIM;
    const __half* khb = kh + (size_t)b * SEQ * KW + hkv * HDIM;
    const __half* vhb = vh + (size_t)b * SEQ * KW + hkv * HDIM;

    for (int i = tid; i < 128 * 16; i += 256) {
        int r = i >> 4, c = i & 15;
        *reinterpret_cast<uint4*>(smem + FA_QHI + SW256(r, c)) =
            *reinterpret_cast<const uint4*>(qhb + (size_t)(q0 + r) * QW + c * 8);
        *reinterpret_cast<uint4*>(smem + FA_QLO + SW256(r, c)) =
            *reinterpret_cast<const uint4*>(qlb + (size_t)(q0 + r) * QW + c * 8);
    }

    const int asel = lane >> 3;
    const int arow = (lane & 7) + ((asel & 1) << 3);
    const int akc  = asel >> 1;
    const int brow = (lane & 7) + ((asel >> 1) << 3);
    const int bkc  = asel & 1;
    const int qrow_s = wid * 16 + arow;

    float o[16][4];
#pragma unroll
    for (int g = 0; g < 16; g++)
#pragma unroll
        for (int e = 0; e < 4; e++) o[g][e] = 0.f;
    float m0 = -1e30f, m1 = -1e30f, l0 = 0.f, l1 = 0.f;

    const int ntiles = 2 * qt + 2;

    auto issueKV = [&](int kt) {
        int k0 = kt * 64;
        uint32_t kb = su + FA_K + (uint32_t)(kt & 1) * 16384u;
        uint32_t vb = su + FA_V + (uint32_t)(kt & 1) * 16384u;
#pragma unroll
        for (int i = 0; i < 4; i++) {
            int id = tid + i * 256;
            int r = id >> 4, c = id & 15;
            size_t go = (size_t)(k0 + r) * KW + c * 8;
            uint32_t so = SW256(r, c);
            cp_async16(kb + so, khb + go);
            cp_async16(vb + so, vhb + go);
        }
        cp_commit();
    };

    issueKV(0);

    const int r0g = q0 + wid * 16 + (lane >> 2);
    const int r1g = r0g + 8;

    for (int kt = 0; kt < ntiles; ++kt) {
        if (kt + 1 < ntiles) { issueKV(kt + 1); cp_wait1(); }
        else                 { cp_wait0(); }
        __syncthreads();

        uint32_t kb = su + FA_K + (uint32_t)(kt & 1) * 16384u;
        uint32_t vb = su + FA_V + (uint32_t)(kt & 1) * 16384u;

        // ---- S = QK^T (fp16, 2 terms) ----
        float s[8][4];
#pragma unroll
        for (int t = 0; t < 8; t++)
#pragma unroll
            for (int e = 0; e < 4; e++) s[t][e] = 0.f;

#pragma unroll
        for (int d = 0; d < 8; ++d) {
            uint32_t ah[4], al[4];
            ldmatrix_x4(ah, su + FA_QHI + SW256(qrow_s, d * 2 + akc));
            ldmatrix_x4(al, su + FA_QLO + SW256(qrow_s, d * 2 + akc));
#pragma unroll
            for (int j = 0; j < 4; ++j) {
                int R = j * 16 + brow;
                uint32_t kf[4];
                ldmatrix_x4(kf, kb + SW256(R, d * 2 + bkc));
                mma_fp16(s[2 * j],     ah, kf[0], kf[1]);
                mma_fp16(s[2 * j + 1], ah, kf[2], kf[3]);
                mma_fp16(s[2 * j],     al, kf[0], kf[1]);
                mma_fp16(s[2 * j + 1], al, kf[2], kf[3]);
            }
        }

        const int k0 = kt * 64;
        const bool dm = (kt >= 2 * qt);
        float mx0 = -1e30f, mx1 = -1e30f;
#pragma unroll
        for (int t = 0; t < 8; t++) {
            int c0 = k0 + t * 8 + (lane & 3) * 2;
            s[t][0] *= scale; s[t][1] *= scale; s[t][2] *= scale; s[t][3] *= scale;
            if (dm) {
                if (c0     > r0g) s[t][0] = -1e30f;
                if (c0 + 1 > r0g) s[t][1] = -1e30f;
                if (c0     > r1g) s[t][2] = -1e30f;
                if (c0 + 1 > r1g) s[t][3] = -1e30f;
            }
            mx0 = fmaxf(mx0, fmaxf(s[t][0], s[t][1]));
            mx1 = fmaxf(mx1, fmaxf(s[t][2], s[t][3]));
        }
        mx0 = fmaxf(mx0, __shfl_xor_sync(0xffffffffu, mx0, 1));
        mx0 = fmaxf(mx0, __shfl_xor_sync(0xffffffffu, mx0, 2));
        mx1 = fmaxf(mx1, __shfl_xor_sync(0xffffffffu, mx1, 1));
        mx1 = fmaxf(mx1, __shfl_xor_sync(0xffffffffu, mx1, 2));

        float mn0 = fmaxf(m0, mx0), mn1 = fmaxf(m1, mx1);
        float a0 = __expf(m0 - mn0), a1 = __expf(m1 - mn1);
        m0 = mn0; m1 = mn1;

        // ---- P = exp(S - m), kept in registers (overwrite s) ----
        float rs0 = 0.f, rs1 = 0.f;
#pragma unroll
        for (int t = 0; t < 8; t++) {
            float p0 = __expf(s[t][0] - m0);
            float p1 = __expf(s[t][1] - m0);
            float p2 = __expf(s[t][2] - m1);
            float p3 = __expf(s[t][3] - m1);
            rs0 += p0 + p1; rs1 += p2 + p3;
            s[t][0] = p0; s[t][1] = p1; s[t][2] = p2; s[t][3] = p3;
        }
        rs0 += __shfl_xor_sync(0xffffffffu, rs0, 1);
        rs0 += __shfl_xor_sync(0xffffffffu, rs0, 2);
        rs1 += __shfl_xor_sync(0xffffffffu, rs1, 1);
        rs1 += __shfl_xor_sync(0xffffffffu, rs1, 2);
        l0 = l0 * a0 + rs0;
        l1 = l1 * a1 + rs1;

        // rescale O
#pragma unroll
        for (int g = 0; g < 16; g++) {
            o[g][0] *= a0; o[g][1] *= a0; o[g][2] *= a1; o[g][3] *= a1;
        }

        // ---- O += (ph + pl) * v, P fragments built in registers ----
        // acc fragment (c0..c3) of tiles s[2ks], s[2ks+1] maps exactly onto the
        // A-operand m16k16 fragment for key-chunk ks.
        const int vrow0 = (lane & 7) + ((asel & 1) << 3);
        const int vkc   = asel >> 1;
#pragma unroll
        for (int ks = 0; ks < 4; ++ks) {
            uint32_t ph[4], pl[4];
            split_pack2(s[2 * ks][0],     s[2 * ks][1],     ph[0], pl[0]);
            split_pack2(s[2 * ks][2],     s[2 * ks][3],     ph[1], pl[1]);
            split_pack2(s[2 * ks + 1][0], s[2 * ks + 1][1], ph[2], pl[2]);
            split_pack2(s[2 * ks + 1][2], s[2 * ks + 1][3], ph[3], pl[3]);
            int vr = ks * 16 + vrow0;
#pragma unroll
            for (int g = 0; g < 8; ++g) {
                uint32_t vf[4];
                ldmatrix_x4_trans(vf, vb + SW256(vr, g * 2 + vkc));
                mma_fp16(o[2 * g],     ph, vf[0], vf[1]);
                mma_fp16(o[2 * g + 1], ph, vf[2], vf[3]);
                mma_fp16(o[2 * g],     pl, vf[0], vf[1]);
                mma_fp16(o[2 * g + 1], pl, vf[2], vf[3]);
            }
        }
        __syncthreads();
    }

    float inv0 = 1.0f / l0, inv1 = 1.0f / l1;
    int row0 = b * SEQ + q0 + wid * 16 + (lane >> 2);
    int row1 = row0 + 8;
#pragma unroll
    for (int g = 0; g < 16; g++) {
        int col = h * HDIM + g * 8 + (lane & 3) * 2;
        float y0 = o[g][0] * inv0, y1 = o[g][1] * inv0;
        float y2 = o[g][2] * inv1, y3 = o[g][3] * inv1;
        store2h(x2, (size_t)row0 * 2048 + col, y0, y1);
        store2h(x2, (size_t)row1 * 2048 + col, y2, y3);
    }
}

// ---------------------------------------------------------------------------
// Launch
// ---------------------------------------------------------------------------
extern "C" void kernel_launch(void* const* d_in, const int* in_sizes, int n_in,
                              void* d_out, int out_size)
{
    const float* x    = (const float*)d_in[0];
    const float* cosp = (const float*)d_in[1];
    const float* sinp = (const float*)d_in[2];
    const float* Wq   = (const float*)d_in[3];
    const float* Wk   = (const float*)d_in[4];
    const float* Wv   = (const float*)d_in[5];
    const float* Wo   = (const float*)d_in[6];
    const float* bo   = (const float*)d_in[7];
    float* out = (float*)d_out;

    __half *x2, *wqkv, *wo2, *qh, *ql, *kh, *vh;
    cudaGetSymbolAddress((void**)&x2,   g_x2);
    cudaGetSymbolAddress((void**)&wqkv, g_wqkv);
    cudaGetSymbolAddress((void**)&wo2,  g_wo2);
    cudaGetSymbolAddress((void**)&qh,   g_qh);
    cudaGetSymbolAddress((void**)&ql,   g_ql);
    cudaGetSymbolAddress((void**)&kh,   g_kh);
    cudaGetSymbolAddress((void**)&vh,   g_vh);

    cudaFuncSetAttribute(hgemm_kernel, cudaFuncAttributeMaxDynamicSharedMemorySize, HG_SMEM);
    cudaFuncSetAttribute(qkv_gemm_kernel, cudaFuncAttributeMaxDynamicSharedMemorySize, HG_SMEM);
    cudaFuncSetAttribute(flash_hmma_kernel, cudaFuncAttributeMaxDynamicSharedMemorySize, FA_SMEM);

    // prep + compute; flash is launch #4 so ncu -s 5 captures it
    tconv_qkv_kernel<<<dim3(64, 64, 3), dim3(32, 8)>>>(Wq, Wk, Wv, wqkv);
    conv2048_kernel<<<MROWS * CDIM / 4 / 256, 256>>>(x, x2);

    // Fused QKV projection + rmsnorm + rope (fp16 single x single GEMM)
    qkv_gemm_kernel<<<dim3(3072 / 128, MROWS / 128), 256, HG_SMEM>>>(
        x2, wqkv, cosp, sinp, qh, ql, kh, vh);

    // fp16 flash attention (register-resident P; writes fp16 output into x2)
    dim3 ga(SEQ / 128, BATCH * NHEAD);
    flash_hmma_kernel<<<ga, 256, FA_SMEM>>>(qh, ql, kh, vh, x2);

    // Wo weight convert (moved after flash; only needed by hgemm)
    tconv_wo_kernel<<<dim3(64, 64), dim3(32, 8)>>>(Wo, wo2);

    // output projection + bias (fp16 single x single GEMM)
    hgemm_kernel<<<dim3(QW / 128, MROWS / 128), 256, HG_SMEM>>>(x2, wo2, out, QW, bo);
}

// round 17
// speedup vs baseline: 1.7184x; 1.1949x over previous
#include <cuda_runtime.h>
#include <cuda_bf16.h>
#include <cuda_fp16.h>
#include <math.h>
#include <stdint.h>

// Problem constants
#define BATCH 2
#define SEQ   2048
#define CDIM  2048
#define NHEAD 16
#define NKV   4
#define HDIM  128
#define HALF  64
#define MROWS (BATCH*SEQ)          // 4096
#define QW    (NHEAD*HDIM)         // 2048
#define KW    (NKV*HDIM)           // 512

// ---------------------------------------------------------------------------
// Scratch (device globals; no allocations allowed)
// ---------------------------------------------------------------------------
__device__ __half g_x2  [4096 * 2048];            // 16 MB fp16 (x; later attn-out)
__device__ __half g_wqkv[3072 * 2048];            // 12 MB packed [Wq|Wk|Wv]^T fp16
__device__ __half g_wo2 [2048 * 2048];            // 8 MB Wo^T fp16
__device__ __half g_qh[MROWS * QW];               // 16 MB fp16 q (single)
__device__ __half g_kh[MROWS * KW];               // 4 MB fp16 k (single)
__device__ __half g_vh[MROWS * KW];               // 4 MB fp16 v (single)

// ---------------------------------------------------------------------------
// Baseline-PTX tensor-core helpers
// ---------------------------------------------------------------------------
__device__ __forceinline__ uint32_t smem_u32_of(const void* p) {
    uint32_t a;
    asm("{ .reg .u64 t; cvta.to.shared.u64 t, %1; cvt.u32.u64 %0, t; }" : "=r"(a) : "l"(p));
    return a;
}
__device__ __forceinline__ void cp_async16(uint32_t saddr, const void* gaddr) {
    asm volatile("cp.async.cg.shared.global [%0], [%1], 16;" :: "r"(saddr), "l"(gaddr));
}
__device__ __forceinline__ void cp_commit() {
    asm volatile("cp.async.commit_group;" ::: "memory");
}
__device__ __forceinline__ void cp_wait0() {
    asm volatile("cp.async.wait_group 0;" ::: "memory");
}
__device__ __forceinline__ void cp_wait1() {
    asm volatile("cp.async.wait_group 1;" ::: "memory");
}
__device__ __forceinline__ void ldmatrix_x4(uint32_t* r, uint32_t addr) {
    asm volatile("ldmatrix.sync.aligned.m8n8.x4.shared.b16 {%0,%1,%2,%3}, [%4];"
                 : "=r"(r[0]), "=r"(r[1]), "=r"(r[2]), "=r"(r[3]) : "r"(addr));
}
__device__ __forceinline__ void ldmatrix_x4_trans(uint32_t* r, uint32_t addr) {
    asm volatile("ldmatrix.sync.aligned.m8n8.x4.trans.shared.b16 {%0,%1,%2,%3}, [%4];"
                 : "=r"(r[0]), "=r"(r[1]), "=r"(r[2]), "=r"(r[3]) : "r"(addr));
}
__device__ __forceinline__ void mma_fp16(float* c, const uint32_t* a, uint32_t b0, uint32_t b1) {
    asm volatile(
        "mma.sync.aligned.m16n8k16.row.col.f32.f16.f16.f32 "
        "{%0,%1,%2,%3}, {%4,%5,%6,%7}, {%8,%9}, {%0,%1,%2,%3};"
        : "+f"(c[0]), "+f"(c[1]), "+f"(c[2]), "+f"(c[3])
        : "r"(a[0]), "r"(a[1]), "r"(a[2]), "r"(a[3]), "r"(b0), "r"(b1));
}

// swizzled smem offsets (16B chunks, XOR row&7)
#define SW256(r, c) ((uint32_t)((r) * 256 + (((c) ^ ((r) & 7)) << 4)))

__device__ __forceinline__ void store2h(__half* o, size_t idx, float a, float b) {
    __half2 hp = {__float2half(a), __float2half(b)};
    *reinterpret_cast<__half2*>(o + idx) = hp;
}
__device__ __forceinline__ uint32_t pack2(float a, float b) {
    __half2 h = {__float2half(a), __float2half(b)};
    return *reinterpret_cast<uint32_t*>(&h);
}

// ===========================================================================
// fp16 GEMM core (single x single): 128x128 CTA tile, 8 warps (4x2),
// warp tile 32x64. A[M,2048] fp16 K-major, B[N,2048] fp16 K-major.
// NIT=32 k-chunks; stage = {A 16K | B 16K}. 2-stage pipeline.
// ===========================================================================
#define HG_STAGE 32768
#define HG_SMEM  (2 * HG_STAGE)
#define HG_NIT   32

struct GemmFrag { float acc[2][8][4]; };

__device__ __forceinline__ void gemm_mainloop(
    const __half* __restrict__ A, const __half* __restrict__ B,
    uint32_t su, int m0, int n0, GemmFrag& F)
{
    const int tid  = threadIdx.x;
    const int wid  = tid >> 5;
    const int lane = tid & 31;

    uint32_t smoff[4];
    const __half *gA[4], *gB[4];
#pragma unroll
    for (int i = 0; i < 4; i++) {
        int id = tid + i * 256;
        int r = id >> 3, c = id & 7;
        smoff[i] = (uint32_t)(r * 128 + ((c ^ (r & 7)) << 4));
        gA[i] = A + (size_t)(m0 + r) * 2048 + c * 8;
        gB[i] = B + (size_t)(n0 + r) * 2048 + c * 8;
    }

    const int mwarp = (wid & 3) * 32;
    const int nwarp = (wid >> 2) * 64;

    const int asel = lane >> 3;
    const int arow = (lane & 7) + ((asel & 1) << 3);
    const int akc  = asel >> 1;
    const int brow = (lane & 7) + ((asel >> 1) << 3);
    const int bkc  = asel & 1;

#pragma unroll
    for (int mf = 0; mf < 2; mf++)
#pragma unroll
        for (int nf = 0; nf < 8; nf++)
#pragma unroll
            for (int e = 0; e < 4; e++) F.acc[mf][nf][e] = 0.f;

    auto issue = [&](int t, int stage) {
        int koff = t * 64;
        uint32_t ab = su + (uint32_t)stage * (uint32_t)HG_STAGE;
        uint32_t bb = ab + 16384u;
#pragma unroll
        for (int i = 0; i < 4; i++) {
            cp_async16(ab + smoff[i], gA[i] + koff);
            cp_async16(bb + smoff[i], gB[i] + koff);
        }
        cp_commit();
    };

    issue(0, 0);
    for (int it = 0; it < HG_NIT; ++it) {
        cp_wait0();
        __syncthreads();
        if (it + 1 < HG_NIT) issue(it + 1, (it + 1) & 1);

        uint32_t ab = su + (uint32_t)(it & 1) * (uint32_t)HG_STAGE;
        uint32_t bb = ab + 16384u;

#pragma unroll
        for (int ks = 0; ks < 4; ++ks) {
            uint32_t br[4][4];
#pragma unroll
            for (int bh = 0; bh < 4; bh++) {
                int R = nwarp + bh * 16 + brow;
                int ch = ks * 2 + bkc;
                ldmatrix_x4(br[bh], bb + R * 128 + (uint32_t)((ch ^ (R & 7)) << 4));
            }
#pragma unroll
            for (int mf = 0; mf < 2; mf++) {
                int R = mwarp + mf * 16 + arow;
                uint32_t off = (uint32_t)(R * 128 + (((ks * 2 + akc) ^ (R & 7)) << 4));
                uint32_t af[4];
                ldmatrix_x4(af, ab + off);
#pragma unroll
                for (int bh = 0; bh < 4; bh++) {
                    mma_fp16(F.acc[mf][2 * bh],     af, br[bh][0], br[bh][1]);
                    mma_fp16(F.acc[mf][2 * bh + 1], af, br[bh][2], br[bh][3]);
                }
            }
        }
    }
}

// ---------------------------------------------------------------------------
// Generic GEMM with fp32 output + optional bias (used for Wo).
// ---------------------------------------------------------------------------
__global__ __launch_bounds__(256, 2)
void hgemm_kernel(const __half* __restrict__ A, const __half* __restrict__ B,
                  float* __restrict__ C, int N, const float* __restrict__ bias)
{
    extern __shared__ __align__(1024) char smem[];
    const uint32_t su = smem_u32_of(smem);
    const int tid  = threadIdx.x;
    const int wid  = tid >> 5;
    const int lane = tid & 31;
    const int m0 = blockIdx.y * 128;
    const int n0 = blockIdx.x * 128;

    GemmFrag F;
    gemm_mainloop(A, B, su, m0, n0, F);

    const int mwarp = (wid & 3) * 32;
    const int nwarp = (wid >> 2) * 64;
    const int mrow = lane >> 2;
    const int ncol = (lane & 3) * 2;
#pragma unroll
    for (int mf = 0; mf < 2; mf++) {
#pragma unroll
        for (int nf = 0; nf < 8; nf++) {
            int gm = m0 + mwarp + mf * 16 + mrow;
            int gn = n0 + nwarp + nf * 8 + ncol;
            float b0 = 0.f, b1 = 0.f;
            if (bias != nullptr) { b0 = bias[gn]; b1 = bias[gn + 1]; }
            float2 lo = make_float2(F.acc[mf][nf][0] + b0, F.acc[mf][nf][1] + b1);
            float2 hi = make_float2(F.acc[mf][nf][2] + b0, F.acc[mf][nf][3] + b1);
            *reinterpret_cast<float2*>(C + (size_t)gm * N + gn)       = lo;
            *reinterpret_cast<float2*>(C + (size_t)(gm + 8) * N + gn) = hi;
        }
    }
}

// ---------------------------------------------------------------------------
// Fused QKV GEMM + per-head RMSNorm + RoPE + fp16 epilogue.
//   cols [0,2048)    -> q heads: rmsnorm+rope -> qh (fp16 single)
//   cols [2048,2560) -> k heads: rmsnorm+rope -> kh (fp16 single)
//   cols [2560,3072) -> v: fp16 single -> vh
// ---------------------------------------------------------------------------
__global__ __launch_bounds__(256, 2)
void qkv_gemm_kernel(const __half* __restrict__ A, const __half* __restrict__ B,
                     const float* __restrict__ cosp, const float* __restrict__ sinp,
                     __half* __restrict__ qh, __half* __restrict__ kh,
                     __half* __restrict__ vh)
{
    extern __shared__ __align__(1024) char smem[];
    const uint32_t su = smem_u32_of(smem);
    const int tid  = threadIdx.x;
    const int wid  = tid >> 5;
    const int lane = tid & 31;
    const int m0 = blockIdx.y * 128;
    const int n0 = blockIdx.x * 128;

    GemmFrag F;
    gemm_mainloop(A, B, su, m0, n0, F);

    const int mwarp = (wid & 3) * 32;
    const int nwarp = (wid >> 2) * 64;
    const int mrow = lane >> 2;
    const int ncol = (lane & 3) * 2;

    if (n0 >= 2560) {
        // V region: single fp16
#pragma unroll
        for (int mf = 0; mf < 2; mf++)
#pragma unroll
            for (int nf = 0; nf < 8; nf++) {
                int gm = m0 + mwarp + mf * 16 + mrow;
                int gn = n0 - 2560 + nwarp + nf * 8 + ncol;
                store2h(vh, (size_t)gm * 512 + gn,       F.acc[mf][nf][0], F.acc[mf][nf][1]);
                store2h(vh, (size_t)(gm + 8) * 512 + gn, F.acc[mf][nf][2], F.acc[mf][nf][3]);
            }
        return;
    }

    // ---- Q/K region: RMSNorm + RoPE, all in-CTA ----
    __syncthreads();   // pipeline smem no longer needed; safe to reuse
    float* nt = reinterpret_cast<float*>(smem);        // [128][128] fp32 = 64K
    __shared__ float ssqp[2][128];
    __shared__ float rmsv[128];

#pragma unroll
    for (int mf = 0; mf < 2; mf++) {
        int lr0 = mwarp + mf * 16 + mrow;
        int lr1 = lr0 + 8;
        float p0 = 0.f, p1 = 0.f;
#pragma unroll
        for (int nf = 0; nf < 8; nf++) {
            int cc = nwarp + nf * 8 + ncol;
            float a0 = F.acc[mf][nf][0], a1 = F.acc[mf][nf][1];
            float a2 = F.acc[mf][nf][2], a3 = F.acc[mf][nf][3];
            nt[lr0 * 128 + cc]     = a0;
            nt[lr0 * 128 + cc + 1] = a1;
            nt[lr1 * 128 + cc]     = a2;
            nt[lr1 * 128 + cc + 1] = a3;
            p0 += a0 * a0 + a1 * a1;
            p1 += a2 * a2 + a3 * a3;
        }
        p0 += __shfl_xor_sync(0xffffffffu, p0, 1);
        p0 += __shfl_xor_sync(0xffffffffu, p0, 2);
        p1 += __shfl_xor_sync(0xffffffffu, p1, 1);
        p1 += __shfl_xor_sync(0xffffffffu, p1, 2);
        if ((lane & 3) == 0) {
            ssqp[wid >> 2][lr0] = p0;
            ssqp[wid >> 2][lr1] = p1;
        }
    }
    __syncthreads();
    if (tid < 128) {
        float s = ssqp[0][tid] + ssqp[1][tid];
        rmsv[tid] = rsqrtf(s * (1.0f / 128.0f) + 1.1920929e-7f);
    }
    __syncthreads();

    // RoPE + store: 2 threads per row, 32 dims each half
    {
        int r = tid >> 1;
        int dbase = (tid & 1) * 32;
        int gm = m0 + r;
        int t  = gm & (SEQ - 1);
        float rm = rmsv[r];
        const bool isq = (n0 < 2048);
        size_t stride = isq ? 2048 : 512;
        int colbase = isq ? n0 : (n0 - 2048);
        size_t rowoff = (size_t)gm * stride + colbase;
        __half* dst = isq ? qh : kh;
        const float* crow = cosp + t * HALF;
        const float* srow = sinp + t * HALF;
        const float* nrow = nt + r * 128;
#pragma unroll 4
        for (int j = 0; j < 32; j += 2) {
            int d = dbase + j;
            float v0a = nrow[d]      * rm, v1a = nrow[d + 64] * rm;
            float v0b = nrow[d + 1]  * rm, v1b = nrow[d + 65] * rm;
            float ca = crow[d],     sa = srow[d];
            float cb = crow[d + 1], sb = srow[d + 1];
            float y0 = v0a * ca - v1a * sa, y1 = v0b * cb - v1b * sb;
            float y2 = v0a * sa + v1a * ca, y3 = v0b * sb + v1b * cb;
            store2h(dst, rowoff + d,      y0, y1);
            store2h(dst, rowoff + 64 + d, y2, y3);
        }
    }
}

// ---------------------------------------------------------------------------
// fp32 -> fp16 convert.
// ---------------------------------------------------------------------------
__global__ void conv2048_kernel(const float* __restrict__ src, __half* __restrict__ dst)
{
    int i = blockIdx.x * 256 + threadIdx.x;
    float4 v = reinterpret_cast<const float4*>(src)[i];
    __half2 a = {__float2half(v.x), __float2half(v.y)};
    __half2 b = {__float2half(v.z), __float2half(v.w)};
    reinterpret_cast<__half2*>(dst)[i * 2]     = a;
    reinterpret_cast<__half2*>(dst)[i * 2 + 1] = b;
}

// ---------------------------------------------------------------------------
// Transposed fp16 convert of W [2048, N] into dst columns [nbase, nbase+N),
// K-major [n][2048].
// ---------------------------------------------------------------------------
__device__ __forceinline__ void tconv_body(const float* __restrict__ W,
                                           __half* __restrict__ dst,
                                           int N, int nbase, int bx, int by)
{
    __shared__ float tl[32][33];
    int tx = threadIdx.x, ty = threadIdx.y;
    int n0 = bx * 32, k0 = by * 32;
#pragma unroll
    for (int j = 0; j < 4; j++)
        tl[ty + j * 8][tx] = W[(size_t)(k0 + ty + j * 8) * N + n0 + tx];
    __syncthreads();
#pragma unroll
    for (int j = 0; j < 4; j++) {
        int n = nbase + n0 + ty + j * 8;
        int k = k0 + tx;
        dst[(size_t)n * 2048 + k] = __float2half(tl[tx][ty + j * 8]);
    }
}

__global__ void tconv_qkv_kernel(const float* __restrict__ Wq, const float* __restrict__ Wk,
                                 const float* __restrict__ Wv, __half* __restrict__ dst)
{
    int z = blockIdx.z;
    const float* W = (z == 0) ? Wq : (z == 1) ? Wk : Wv;
    int N     = (z == 0) ? 2048 : 512;
    int nbase = (z == 0) ? 0 : (z == 1) ? 2048 : 2560;
    if ((int)blockIdx.x * 32 >= N) return;
    tconv_body(W, dst, N, nbase, blockIdx.x, blockIdx.y);
}

__global__ void tconv_wo_kernel(const float* __restrict__ W, __half* __restrict__ dst)
{
    tconv_body(W, dst, 2048, 0, blockIdx.x, blockIdx.y);
}

// ---------------------------------------------------------------------------
// fp16 HMMA flash attention, causal, GQA — single-precision fp16 operands.
//   S = q*k (1 term).  O += p*v (1 term, P packed in registers).
// Smem: Q 32K | K 2st 32K | V 2st 32K = 96K
// ---------------------------------------------------------------------------
#define FA_Q   0
#define FA_K   32768
#define FA_V   65536
#define FA_SMEM 98304

__global__ __launch_bounds__(256, 1)
void flash_hmma_kernel(const __half* __restrict__ qh, const __half* __restrict__ kh,
                       const __half* __restrict__ vh, __half* __restrict__ x2)
{
    extern __shared__ __align__(1024) char smem[];
    const uint32_t su = smem_u32_of(smem);
    const int tid  = threadIdx.x;
    const int wid  = tid >> 5;
    const int lane = tid & 31;

    const int qt = (int)gridDim.x - 1 - (int)blockIdx.x;   // long CTAs first
    const int bh = blockIdx.y;
    const int b  = bh >> 4;
    const int h  = bh & 15;
    const int hkv = h >> 2;
    const int q0 = qt * 128;
    const float scale = 0.08838834764831845f;   // 1/sqrt(128)

    const __half* qhb = qh + (size_t)b * SEQ * QW + h * HDIM;
    const __half* khb = kh + (size_t)b * SEQ * KW + hkv * HDIM;
    const __half* vhb = vh + (size_t)b * SEQ * KW + hkv * HDIM;

    for (int i = tid; i < 128 * 16; i += 256) {
        int r = i >> 4, c = i & 15;
        *reinterpret_cast<uint4*>(smem + FA_Q + SW256(r, c)) =
            *reinterpret_cast<const uint4*>(qhb + (size_t)(q0 + r) * QW + c * 8);
    }

    const int asel = lane >> 3;
    const int arow = (lane & 7) + ((asel & 1) << 3);
    const int akc  = asel >> 1;
    const int brow = (lane & 7) + ((asel >> 1) << 3);
    const int bkc  = asel & 1;
    const int qrow_s = wid * 16 + arow;

    float o[16][4];
#pragma unroll
    for (int g = 0; g < 16; g++)
#pragma unroll
        for (int e = 0; e < 4; e++) o[g][e] = 0.f;
    float m0 = -1e30f, m1 = -1e30f, l0 = 0.f, l1 = 0.f;

    const int ntiles = 2 * qt + 2;

    auto issueKV = [&](int kt) {
        int k0 = kt * 64;
        uint32_t kb = su + FA_K + (uint32_t)(kt & 1) * 16384u;
        uint32_t vb = su + FA_V + (uint32_t)(kt & 1) * 16384u;
#pragma unroll
        for (int i = 0; i < 4; i++) {
            int id = tid + i * 256;
            int r = id >> 4, c = id & 15;
            size_t go = (size_t)(k0 + r) * KW + c * 8;
            uint32_t so = SW256(r, c);
            cp_async16(kb + so, khb + go);
            cp_async16(vb + so, vhb + go);
        }
        cp_commit();
    };

    issueKV(0);

    const int r0g = q0 + wid * 16 + (lane >> 2);
    const int r1g = r0g + 8;

    for (int kt = 0; kt < ntiles; ++kt) {
        if (kt + 1 < ntiles) { issueKV(kt + 1); cp_wait1(); }
        else                 { cp_wait0(); }
        __syncthreads();

        uint32_t kb = su + FA_K + (uint32_t)(kt & 1) * 16384u;
        uint32_t vb = su + FA_V + (uint32_t)(kt & 1) * 16384u;

        // ---- S = QK^T (fp16, 1 term) ----
        float s[8][4];
#pragma unroll
        for (int t = 0; t < 8; t++)
#pragma unroll
            for (int e = 0; e < 4; e++) s[t][e] = 0.f;

#pragma unroll
        for (int d = 0; d < 8; ++d) {
            uint32_t aq[4];
            ldmatrix_x4(aq, su + FA_Q + SW256(qrow_s, d * 2 + akc));
#pragma unroll
            for (int j = 0; j < 4; ++j) {
                int R = j * 16 + brow;
                uint32_t kf[4];
                ldmatrix_x4(kf, kb + SW256(R, d * 2 + bkc));
                mma_fp16(s[2 * j],     aq, kf[0], kf[1]);
                mma_fp16(s[2 * j + 1], aq, kf[2], kf[3]);
            }
        }

        const int k0 = kt * 64;
        const bool dm = (kt >= 2 * qt);
        float mx0 = -1e30f, mx1 = -1e30f;
#pragma unroll
        for (int t = 0; t < 8; t++) {
            int c0 = k0 + t * 8 + (lane & 3) * 2;
            s[t][0] *= scale; s[t][1] *= scale; s[t][2] *= scale; s[t][3] *= scale;
            if (dm) {
                if (c0     > r0g) s[t][0] = -1e30f;
                if (c0 + 1 > r0g) s[t][1] = -1e30f;
                if (c0     > r1g) s[t][2] = -1e30f;
                if (c0 + 1 > r1g) s[t][3] = -1e30f;
            }
            mx0 = fmaxf(mx0, fmaxf(s[t][0], s[t][1]));
            mx1 = fmaxf(mx1, fmaxf(s[t][2], s[t][3]));
        }
        mx0 = fmaxf(mx0, __shfl_xor_sync(0xffffffffu, mx0, 1));
        mx0 = fmaxf(mx0, __shfl_xor_sync(0xffffffffu, mx0, 2));
        mx1 = fmaxf(mx1, __shfl_xor_sync(0xffffffffu, mx1, 1));
        mx1 = fmaxf(mx1, __shfl_xor_sync(0xffffffffu, mx1, 2));

        float mn0 = fmaxf(m0, mx0), mn1 = fmaxf(m1, mx1);
        float a0 = __expf(m0 - mn0), a1 = __expf(m1 - mn1);
        m0 = mn0; m1 = mn1;

        // ---- P = exp(S - m), kept in registers ----
        float rs0 = 0.f, rs1 = 0.f;
#pragma unroll
        for (int t = 0; t < 8; t++) {
            float p0 = __expf(s[t][0] - m0);
            float p1 = __expf(s[t][1] - m0);
            float p2 = __expf(s[t][2] - m1);
            float p3 = __expf(s[t][3] - m1);
            rs0 += p0 + p1; rs1 += p2 + p3;
            s[t][0] = p0; s[t][1] = p1; s[t][2] = p2; s[t][3] = p3;
        }
        rs0 += __shfl_xor_sync(0xffffffffu, rs0, 1);
        rs0 += __shfl_xor_sync(0xffffffffu, rs0, 2);
        rs1 += __shfl_xor_sync(0xffffffffu, rs1, 1);
        rs1 += __shfl_xor_sync(0xffffffffu, rs1, 2);
        l0 = l0 * a0 + rs0;
        l1 = l1 * a1 + rs1;

        // rescale O
#pragma unroll
        for (int g = 0; g < 16; g++) {
            o[g][0] *= a0; o[g][1] *= a0; o[g][2] *= a1; o[g][3] *= a1;
        }

        // ---- O += p * v, P fragments packed in registers ----
        const int vrow0 = (lane & 7) + ((asel & 1) << 3);
        const int vkc   = asel >> 1;
#pragma unroll
        for (int ks = 0; ks < 4; ++ks) {
            uint32_t ph[4];
            ph[0] = pack2(s[2 * ks][0],     s[2 * ks][1]);
            ph[1] = pack2(s[2 * ks][2],     s[2 * ks][3]);
            ph[2] = pack2(s[2 * ks + 1][0], s[2 * ks + 1][1]);
            ph[3] = pack2(s[2 * ks + 1][2], s[2 * ks + 1][3]);
            int vr = ks * 16 + vrow0;
#pragma unroll
            for (int g = 0; g < 8; ++g) {
                uint32_t vf[4];
                ldmatrix_x4_trans(vf, vb + SW256(vr, g * 2 + vkc));
                mma_fp16(o[2 * g],     ph, vf[0], vf[1]);
                mma_fp16(o[2 * g + 1], ph, vf[2], vf[3]);
            }
        }
        __syncthreads();
    }

    float inv0 = 1.0f / l0, inv1 = 1.0f / l1;
    int row0 = b * SEQ + q0 + wid * 16 + (lane >> 2);
    int row1 = row0 + 8;
#pragma unroll
    for (int g = 0; g < 16; g++) {
        int col = h * HDIM + g * 8 + (lane & 3) * 2;
        float y0 = o[g][0] * inv0, y1 = o[g][1] * inv0;
        float y2 = o[g][2] * inv1, y3 = o[g][3] * inv1;
        store2h(x2, (size_t)row0 * 2048 + col, y0, y1);
        store2h(x2, (size_t)row1 * 2048 + col, y2, y3);
    }
}

// ---------------------------------------------------------------------------
// Launch
// ---------------------------------------------------------------------------
extern "C" void kernel_launch(void* const* d_in, const int* in_sizes, int n_in,
                              void* d_out, int out_size)
{
    const float* x    = (const float*)d_in[0];
    const float* cosp = (const float*)d_in[1];
    const float* sinp = (const float*)d_in[2];
    const float* Wq   = (const float*)d_in[3];
    const float* Wk   = (const float*)d_in[4];
    const float* Wv   = (const float*)d_in[5];
    const float* Wo   = (const float*)d_in[6];
    const float* bo   = (const float*)d_in[7];
    float* out = (float*)d_out;

    __half *x2, *wqkv, *wo2, *qh, *kh, *vh;
    cudaGetSymbolAddress((void**)&x2,   g_x2);
    cudaGetSymbolAddress((void**)&wqkv, g_wqkv);
    cudaGetSymbolAddress((void**)&wo2,  g_wo2);
    cudaGetSymbolAddress((void**)&qh,   g_qh);
    cudaGetSymbolAddress((void**)&kh,   g_kh);
    cudaGetSymbolAddress((void**)&vh,   g_vh);

    cudaFuncSetAttribute(hgemm_kernel, cudaFuncAttributeMaxDynamicSharedMemorySize, HG_SMEM);
    cudaFuncSetAttribute(qkv_gemm_kernel, cudaFuncAttributeMaxDynamicSharedMemorySize, HG_SMEM);
    cudaFuncSetAttribute(flash_hmma_kernel, cudaFuncAttributeMaxDynamicSharedMemorySize, FA_SMEM);

    // prep + compute; flash is launch #4 so ncu -s 5 captures it
    tconv_qkv_kernel<<<dim3(64, 64, 3), dim3(32, 8)>>>(Wq, Wk, Wv, wqkv);
    conv2048_kernel<<<MROWS * CDIM / 4 / 256, 256>>>(x, x2);

    // Fused QKV projection + rmsnorm + rope (fp16 single x single GEMM)
    qkv_gemm_kernel<<<dim3(3072 / 128, MROWS / 128), 256, HG_SMEM>>>(
        x2, wqkv, cosp, sinp, qh, kh, vh);

    // fp16 flash attention (single-operand; writes fp16 output into x2)
    dim3 ga(SEQ / 128, BATCH * NHEAD);
    flash_hmma_kernel<<<ga, 256, FA_SMEM>>>(qh, kh, vh, x2);

    // Wo weight convert
    tconv_wo_kernel<<<dim3(64, 64), dim3(32, 8)>>>(Wo, wo2);

    // output projection + bias (fp16 single x single GEMM)
    hgemm_kernel<<<dim3(QW / 128, MROWS / 128), 256, HG_SMEM>>>(x2, wo2, out, QW, bo);
}